// round 12
// baseline (speedup 1.0000x reference)
#include <cuda_runtime.h>
#include <cuda_fp16.h>
#include <cuda_bf16.h>
#include <cstdint>

// ---------------- problem constants ----------------
#define B_SZ   2
#define L_SZ   2048
#define DM     1024      // d_model
#define DI     2048      // d_inner
#define DS     128       // d_state
#define DCONV  4
#define NH     32        // nheads
#define HD     64        // headdim
#define DTIME  64
#define CD     (DI + 2*DS)            // 2304 conv dim
#define DIP    (2*DI + 2*DS + NH)     // 4384 in-proj dim
#define DIPPAD 4480                   // 35*128
#define NGEMM2 4352                   // 34*128 = DI+CD (z,xBC cols only)
#define ROWS   (B_SZ*L_SZ)            // 4096
#define NC     16                     // scan chunks
#define CL     (L_SZ/NC)              // 128 chunk len
#define EPSV   1e-5f

// ---------------- scratch (device globals; no allocs allowed) ----------------
__device__ __half g_uhi[ROWS*DM];
__device__ __half g_zxh[ROWS*NGEMM2];      // GEMM2 output (z + xBC pre-conv), fp16
__device__ __half g_xBCh[ROWS*CD];         // conv+silu output, fp16
__device__ float  g_dt[ROWS*NH];
__device__ float  g_dtA[ROWS*NH];
__device__ float  g_cumdec[B_SZ*NH*L_SZ];
__device__ float  g_logcum[B_SZ*NH*L_SZ];
__device__ __half g_SfinalH[B_SZ*NH*NC*HD*DS];
__device__ __half g_HinitH [B_SZ*NH*NC*HD*DS];
__device__ __half g_yh[ROWS*DI];
__device__ __half g_yhi[ROWS*DI];
__device__ __half g_hhi[ROWS*DM], g_hlo[ROWS*DM];
__device__ __half g_wpt_hi[DM*DM];                    // W_proj^T [1024][1024] (hi only)
__device__ __half g_wit_hi[DIPPAD*DM];                // W_in^T   [4480][1024] (hi only)
__device__ __half g_wot_hi[DM*DI];                    // W_out^T  [1024][2048] (hi only)
__device__ float  g_wd2[DM*NH];                       // W_proj @ W_in[:,dt cols]
__device__ float  g_bd2[NH];                          // b_proj . W_in[:,dt cols]

// ---------------- mma / ldmatrix helpers ----------------
__device__ __forceinline__ void mma16(float& d0, float& d1, float& d2, float& d3,
                                      uint32_t a0, uint32_t a1, uint32_t a2, uint32_t a3,
                                      uint32_t b0, uint32_t b1)
{
    asm volatile("mma.sync.aligned.m16n8k16.row.col.f32.f16.f16.f32 "
        "{%0,%1,%2,%3},{%4,%5,%6,%7},{%8,%9},{%0,%1,%2,%3};"
        : "+f"(d0), "+f"(d1), "+f"(d2), "+f"(d3)
        : "r"(a0), "r"(a1), "r"(a2), "r"(a3), "r"(b0), "r"(b1));
}
#define LDSM4(r0,r1,r2,r3, addr) \
    asm volatile("ldmatrix.sync.aligned.m8n8.x4.shared.b16 {%0,%1,%2,%3}, [%4];" \
        : "=r"(r0), "=r"(r1), "=r"(r2), "=r"(r3) : "r"(addr))

// smem geometry (GEMMs): rows of 64 halfs padded to 72 (144B stride)
#define HSTRIDE 72
#define TBYTES  (128 * HSTRIDE * 2)       // 18432 bytes per tensor per stage
#define STAGEB2 (3 * TBYTES)              // Ahi,Alo,Bhi (2-pass)
#define SMEM2P  (2 * STAGEB2)             // 110592 -> 2 CTAs/SM
#define STAGEB1 (2 * TBYTES)              // Ahi,Bhi (1-pass)
#define SMEM1P  (2 * STAGEB1)             // 73728 -> 2 CTAs/SM

// scan-tile smem geometry: rows of 128 halfs padded to 136
#define HS2 136

// ============ 2-pass split-FP16 GEMM (GEMM1; 3 tensors, 2 CTAs/SM) ==========
// u = (Ahi+Alo)[M,K] @ Bhi^T + bias, fp16 output.
__global__ void __launch_bounds__(256, 2) gemm_h2p(
    const __half* __restrict__ Ahi, const __half* __restrict__ Alo,
    const __half* __restrict__ Bhi, const float* __restrict__ bias,
    __half* __restrict__ Hout, int M, int Nreal, int K)
{
    extern __shared__ __align__(16) char smem[];
    const uint32_t sb = (uint32_t)__cvta_generic_to_shared(smem);
    const int tid = threadIdx.x;
    const int wid = tid >> 5;
    const int lane = tid & 31;
    const int wm = wid & 1;
    const int wn = wid >> 1;
    const int r = lane >> 2;
    const int c = lane & 3;
    const int m0 = blockIdx.y << 7;
    const int n0 = blockIdx.x << 7;
    const int nsteps = K >> 6;

    auto load_stage = [&](int kstep, int s) {
        const int k0 = kstep << 6;
        #pragma unroll
        for (int j = 0; j < 12; j++) {
            const int t = j >> 2;
            const __half* gsel = (t == 0) ? Ahi : (t == 1) ? Alo : Bhi;
            const int rb = (t < 2) ? m0 : n0;
            int rem = ((j & 3) << 8) + tid;
            int row = rem >> 3, col = rem & 7;
            const __half* gp = gsel + (size_t)(rb + row) * K + k0 + (col << 3);
            uint32_t sa = sb + (uint32_t)(s * STAGEB2 + t * TBYTES + row * (HSTRIDE * 2) + (col << 4));
            asm volatile("cp.async.cg.shared.global [%0], [%1], 16;" :: "r"(sa), "l"(gp) : "memory");
        }
        asm volatile("cp.async.commit_group;" ::: "memory");
    };

    float acc[4][4][4];
    #pragma unroll
    for (int i = 0; i < 4; i++)
        #pragma unroll
        for (int j = 0; j < 4; j++)
            #pragma unroll
            for (int q = 0; q < 4; q++) acc[i][j][q] = 0.f;

    const int lrow = lane & 15;
    const int lk16 = (lane >> 4) << 4;
    uint32_t arow_off[4], brow_off[2];
    #pragma unroll
    for (int mt = 0; mt < 4; mt++)
        arow_off[mt] = (uint32_t)((wm * 64 + mt * 16 + lrow) * (HSTRIDE * 2)) + (uint32_t)lk16;
    #pragma unroll
    for (int g = 0; g < 2; g++)
        brow_off[g] = (uint32_t)((wn * 32 + g * 16 + lrow) * (HSTRIDE * 2)) + (uint32_t)lk16;

    load_stage(0, 0);

    for (int i = 0; i < nsteps; i++) {
        if (i + 1 < nsteps) {
            load_stage(i + 1, (i + 1) & 1);
            asm volatile("cp.async.wait_group 1;" ::: "memory");
        } else {
            asm volatile("cp.async.wait_group 0;" ::: "memory");
        }
        __syncthreads();

        const int s = i & 1;
        const uint32_t stA_hi = sb + (uint32_t)(s * STAGEB2);
        const uint32_t stA_lo = stA_hi + TBYTES;
        const uint32_t stB_hi = stA_hi + 2 * TBYTES;

        #pragma unroll
        for (int kb = 0; kb < 4; kb++) {
            const uint32_t koff = (uint32_t)(kb << 5);
            uint32_t ah[4][4], al[4][4], bh[4][2];
            #pragma unroll
            for (int mt = 0; mt < 4; mt++) {
                LDSM4(ah[mt][0], ah[mt][1], ah[mt][2], ah[mt][3], stA_hi + arow_off[mt] + koff);
                LDSM4(al[mt][0], al[mt][1], al[mt][2], al[mt][3], stA_lo + arow_off[mt] + koff);
            }
            #pragma unroll
            for (int g = 0; g < 2; g++) {
                uint32_t r0, r1, r2, r3;
                LDSM4(r0, r1, r2, r3, stB_hi + brow_off[g] + koff);
                bh[2*g][0] = r0; bh[2*g+1][0] = r1; bh[2*g][1] = r2; bh[2*g+1][1] = r3;
            }
            #pragma unroll
            for (int mt = 0; mt < 4; mt++)
                #pragma unroll
                for (int nt = 0; nt < 4; nt++) {
                    float* d = acc[mt][nt];
                    mma16(d[0], d[1], d[2], d[3],
                          ah[mt][0], ah[mt][1], ah[mt][2], ah[mt][3], bh[nt][0], bh[nt][1]);
                    mma16(d[0], d[1], d[2], d[3],
                          al[mt][0], al[mt][1], al[mt][2], al[mt][3], bh[nt][0], bh[nt][1]);
                }
        }
        __syncthreads();
    }

    #pragma unroll
    for (int mt = 0; mt < 4; mt++) {
        const int row = m0 + wm * 64 + mt * 16 + r;
        #pragma unroll
        for (int nt = 0; nt < 4; nt++) {
            const int col = n0 + wn * 32 + nt * 8 + 2 * c;
            if (col < Nreal) {
                float b0 = bias[col], b1 = bias[col + 1];
                *(half2*)&Hout[(size_t)row * Nreal + col] =
                    __halves2half2(__float2half_rn(acc[mt][nt][0] + b0),
                                   __float2half_rn(acc[mt][nt][1] + b1));
                *(half2*)&Hout[(size_t)(row + 8) * Nreal + col] =
                    __halves2half2(__float2half_rn(acc[mt][nt][2] + b0),
                                   __float2half_rn(acc[mt][nt][3] + b1));
            }
        }
    }
}

// ============ 1-pass FP16 GEMM (GEMM2/3; 2 tensors, 2 CTAs/SM) ===============
template<bool HOUT>
__global__ void __launch_bounds__(256, 2) gemm_h1(
    const __half* __restrict__ Ahi, const __half* __restrict__ Bhi,
    float* __restrict__ Cout, __half* __restrict__ HoutP,
    int M, int Nreal, int K)
{
    extern __shared__ __align__(16) char smem[];
    const uint32_t sb = (uint32_t)__cvta_generic_to_shared(smem);
    const int tid = threadIdx.x;
    const int wid = tid >> 5;
    const int lane = tid & 31;
    const int wm = wid & 1;
    const int wn = wid >> 1;
    const int r = lane >> 2;
    const int c = lane & 3;
    const int m0 = blockIdx.y << 7;
    const int n0 = blockIdx.x << 7;
    const int nsteps = K >> 6;

    auto load_stage = [&](int kstep, int s) {
        const int k0 = kstep << 6;
        #pragma unroll
        for (int j = 0; j < 8; j++) {
            const int t = j >> 2;
            const __half* gsel = (t == 0) ? Ahi : Bhi;
            const int rb = (t == 0) ? m0 : n0;
            int rem = ((j & 3) << 8) + tid;
            int row = rem >> 3, col = rem & 7;
            const __half* gp = gsel + (size_t)(rb + row) * K + k0 + (col << 3);
            uint32_t sa = sb + (uint32_t)(s * STAGEB1 + t * TBYTES + row * (HSTRIDE * 2) + (col << 4));
            asm volatile("cp.async.cg.shared.global [%0], [%1], 16;" :: "r"(sa), "l"(gp) : "memory");
        }
        asm volatile("cp.async.commit_group;" ::: "memory");
    };

    float acc[4][4][4];
    #pragma unroll
    for (int i = 0; i < 4; i++)
        #pragma unroll
        for (int j = 0; j < 4; j++)
            #pragma unroll
            for (int q = 0; q < 4; q++) acc[i][j][q] = 0.f;

    const int lrow = lane & 15;
    const int lk16 = (lane >> 4) << 4;
    uint32_t arow_off[4], brow_off[2];
    #pragma unroll
    for (int mt = 0; mt < 4; mt++)
        arow_off[mt] = (uint32_t)((wm * 64 + mt * 16 + lrow) * (HSTRIDE * 2)) + (uint32_t)lk16;
    #pragma unroll
    for (int g = 0; g < 2; g++)
        brow_off[g] = (uint32_t)((wn * 32 + g * 16 + lrow) * (HSTRIDE * 2)) + (uint32_t)lk16;

    load_stage(0, 0);

    for (int i = 0; i < nsteps; i++) {
        if (i + 1 < nsteps) {
            load_stage(i + 1, (i + 1) & 1);
            asm volatile("cp.async.wait_group 1;" ::: "memory");
        } else {
            asm volatile("cp.async.wait_group 0;" ::: "memory");
        }
        __syncthreads();

        const int s = i & 1;
        const uint32_t stA = sb + (uint32_t)(s * STAGEB1);
        const uint32_t stB = stA + TBYTES;

        #pragma unroll
        for (int kb = 0; kb < 4; kb++) {
            const uint32_t koff = (uint32_t)(kb << 5);
            uint32_t ah[4][4], bh[4][2];
            #pragma unroll
            for (int mt = 0; mt < 4; mt++)
                LDSM4(ah[mt][0], ah[mt][1], ah[mt][2], ah[mt][3], stA + arow_off[mt] + koff);
            #pragma unroll
            for (int g = 0; g < 2; g++) {
                uint32_t r0, r1, r2, r3;
                LDSM4(r0, r1, r2, r3, stB + brow_off[g] + koff);
                bh[2*g][0] = r0; bh[2*g+1][0] = r1; bh[2*g][1] = r2; bh[2*g+1][1] = r3;
            }
            #pragma unroll
            for (int mt = 0; mt < 4; mt++)
                #pragma unroll
                for (int nt = 0; nt < 4; nt++) {
                    float* d = acc[mt][nt];
                    mma16(d[0], d[1], d[2], d[3],
                          ah[mt][0], ah[mt][1], ah[mt][2], ah[mt][3], bh[nt][0], bh[nt][1]);
                }
        }
        __syncthreads();
    }

    #pragma unroll
    for (int mt = 0; mt < 4; mt++) {
        const int row = m0 + wm * 64 + mt * 16 + r;
        #pragma unroll
        for (int nt = 0; nt < 4; nt++) {
            const int col = n0 + wn * 32 + nt * 8 + 2 * c;
            if (col < Nreal) {
                if (HOUT) {
                    *(half2*)&HoutP[(size_t)row * Nreal + col] =
                        __halves2half2(__float2half_rn(acc[mt][nt][0]), __float2half_rn(acc[mt][nt][1]));
                    *(half2*)&HoutP[(size_t)(row + 8) * Nreal + col] =
                        __halves2half2(__float2half_rn(acc[mt][nt][2]), __float2half_rn(acc[mt][nt][3]));
                } else {
                    *(float2*)&Cout[(size_t)row * Nreal + col] =
                        make_float2(acc[mt][nt][0], acc[mt][nt][1]);
                    *(float2*)&Cout[(size_t)(row + 8) * Nreal + col] =
                        make_float2(acc[mt][nt][2], acc[mt][nt][3]);
                }
            }
        }
    }
}

// ---------------- elementwise split: float -> (hi, lo) fp16 pair -------------
__global__ void split4h_kernel(const float* __restrict__ x,
                               __half* __restrict__ hi, __half* __restrict__ lo, int n4)
{
    int i = blockIdx.x * blockDim.x + threadIdx.x;
    if (i >= n4) return;
    float4 v = ((const float4*)x)[i];
    __half h0 = __float2half_rn(v.x), h1 = __float2half_rn(v.y);
    __half h2 = __float2half_rn(v.z), h3 = __float2half_rn(v.w);
    ((half2*)hi)[2*i]   = __halves2half2(h0, h1);
    ((half2*)hi)[2*i+1] = __halves2half2(h2, h3);
    ((half2*)lo)[2*i]   = __halves2half2(__float2half_rn(v.x - __half2float(h0)),
                                         __float2half_rn(v.y - __half2float(h1)));
    ((half2*)lo)[2*i+1] = __halves2half2(__float2half_rn(v.z - __half2float(h2)),
                                         __float2half_rn(v.w - __half2float(h3)));
}

// ---------------- transpose: W[K,N] -> Wt_hi[Npad,K] fp16 --------------------
__global__ void tsplit_kernel(const float* __restrict__ W,
                              __half* __restrict__ Thi, int K, int N)
{
    __shared__ float t[32][33];
    const int n0 = blockIdx.x * 32, k0 = blockIdx.y * 32;
    const int tx = threadIdx.x, ty = threadIdx.y;
    #pragma unroll
    for (int r = 0; r < 4; r++) {
        int k = k0 + ty + r * 8, n = n0 + tx;
        t[ty + r * 8][tx] = (n < N) ? W[(size_t)k * N + n] : 0.f;
    }
    __syncthreads();
    #pragma unroll
    for (int r = 0; r < 4; r++) {
        int n = n0 + ty + r * 8, k = k0 + tx;
        Thi[(size_t)n * K + k] = __float2half_rn(t[tx][ty + r * 8]);
    }
}

// ---------------- Wd2 = W_proj @ W_in[:,dt cols]; bd2 = b_proj . same --------
__global__ void __launch_bounds__(256) wd2_kernel(
    const float* __restrict__ W_proj, const float* __restrict__ W_in,
    const float* __restrict__ b_proj)
{
    __shared__ float wp[8][1024];    // 8 rows of W_proj
    const int row0 = blockIdx.x * 8;
    const int tid = threadIdx.x;
    for (int idx = tid; idx < 8 * 1024; idx += 256) {
        int r = idx >> 10, j = idx & 1023;
        wp[r][j] = W_proj[(size_t)(row0 + r) * DM + j];
    }
    __syncthreads();
    const int r = tid >> 5, h = tid & 31;
    const float* wcol = W_in + (DI + CD) + h;
    float a0 = 0.f, a1 = 0.f, a2 = 0.f, a3 = 0.f;
    #pragma unroll 4
    for (int j = 0; j < DM; j += 4) {
        a0 = fmaf(wp[r][j+0], wcol[(size_t)(j+0) * DIP], a0);
        a1 = fmaf(wp[r][j+1], wcol[(size_t)(j+1) * DIP], a1);
        a2 = fmaf(wp[r][j+2], wcol[(size_t)(j+2) * DIP], a2);
        a3 = fmaf(wp[r][j+3], wcol[(size_t)(j+3) * DIP], a3);
    }
    g_wd2[(row0 + r) * NH + h] = (a0 + a1) + (a2 + a3);
    if (blockIdx.x == 0 && tid < 32) {
        float s = 0.f;
        for (int j = 0; j < DM; j++)
            s = fmaf(b_proj[j], wcol[(size_t)j * DIP], s);
        g_bd2[tid] = s;
    }
}

// ---------------- dt: exact fp32 from hidden; stores dt, dt*A ----------------
__global__ void __launch_bounds__(256) dt_kernel(
    const float* __restrict__ hidden,
    const float* __restrict__ dte, const float* __restrict__ Wd,
    const float* __restrict__ bd,
    const float* __restrict__ dt_bias, const float* __restrict__ A_log)
{
    __shared__ float us[8][1024];
    const int row0 = blockIdx.x * 8;
    const int tid = threadIdx.x;
    for (int idx = tid; idx < 8 * 1024; idx += 256) {
        int r = idx >> 10, j = idx & 1023;
        us[r][j] = hidden[(size_t)(row0 + r) * DM + j];
    }
    __syncthreads();
    const int r = tid >> 5, h = tid & 31;
    const int row = row0 + r;
    float s = bd[h] + g_bd2[h];
    #pragma unroll 8
    for (int j = 0; j < DTIME; j++) s = fmaf(dte[(size_t)row * DTIME + j], Wd[j * NH + h], s);
    float x0 = 0.f, x1 = 0.f, x2 = 0.f, x3 = 0.f;
    #pragma unroll 4
    for (int j = 0; j < DM; j += 4) {
        x0 = fmaf(us[r][j+0], g_wd2[(j+0) * NH + h], x0);
        x1 = fmaf(us[r][j+1], g_wd2[(j+1) * NH + h], x1);
        x2 = fmaf(us[r][j+2], g_wd2[(j+2) * NH + h], x2);
        x3 = fmaf(us[r][j+3], g_wd2[(j+3) * NH + h], x3);
    }
    float x = (x0 + x1) + (x2 + x3) + dt_bias[h] + s;
    float dt = (x > 20.f) ? x : log1pf(expf(x));
    float A  = -expf(A_log[h]);
    const int idx = row * NH + h;
    g_dt[idx]  = dt;
    g_dtA[idx] = dt * A;
}

// ---------------- causal conv (taps=4) + bias + silu; fp16 in/out ------------
__global__ void conv_kernel(const float* __restrict__ conv_w,
                            const float* __restrict__ conv_b)
{
    int idx = blockIdx.x * blockDim.x + threadIdx.x;
    if (idx >= ROWS * CD) return;
    int c   = idx % CD;
    int row = idx / CD;
    int l   = row & (L_SZ - 1);
    int b   = row / L_SZ;
    float acc = conv_b[c];
    #pragma unroll
    for (int k = 0; k < DCONV; k++) {
        int ll = l - (DCONV - 1) + k;
        if (ll >= 0)
            acc = fmaf(__half2float(g_zxh[(size_t)(b*L_SZ + ll) * NGEMM2 + DI + c]),
                       conv_w[k*CD + c], acc);
    }
    g_xBCh[idx] = __float2half_rn(acc / (1.f + expf(-acc)));
}

// ================= chunk_state: logcum/cumdec + Sfinal = Xw^T @ B ===========
#define CS_SXTW 0
#define CS_SBT  (64*HS2*2)                 // 17408
#define CS_LCS  (CS_SBT + 128*HS2*2)       // 52224
#define CS_DTV  (CS_LCS + 512)
#define CS_WQ   (CS_DTV + 512)
#define CS_SMEM (CS_WQ + 512)              // 53760
__global__ void __launch_bounds__(256, 2) chunk_state_kernel()
{
    extern __shared__ __align__(16) char sm[];
    __half* sXTw = (__half*)(sm + CS_SXTW);
    __half* sBT  = (__half*)(sm + CS_SBT);
    float*  lcs  = (float*)(sm + CS_LCS);
    float*  dtv  = (float*)(sm + CS_DTV);
    float*  wq   = (float*)(sm + CS_WQ);
    const uint32_t sb = (uint32_t)__cvta_generic_to_shared(sm);

    const int c = blockIdx.x, h = blockIdx.y, b = blockIdx.z;
    const int t = threadIdx.x;
    const int l0 = c * CL;
    const int bh = b * NH + h;

    for (int idx = t; idx < CL * DS; idx += 256) {
        int j = idx >> 7, n = idx & 127;
        sBT[n * HS2 + j] = g_xBCh[(size_t)(b*L_SZ + l0 + j) * CD + DI + n];
    }
    if (t < CL) {
        dtv[t] = g_dt [(b*L_SZ + l0 + t) * NH + h];
        lcs[t] = g_dtA[(b*L_SZ + l0 + t) * NH + h];
    }
    __syncthreads();
    for (int off = 1; off < CL; off <<= 1) {
        float cur = 0.f, v = 0.f;
        if (t < CL) { cur = lcs[t]; if (t >= off) v = lcs[t - off]; }
        __syncthreads();
        if (t < CL) lcs[t] = cur + v;
        __syncthreads();
    }
    if (t < CL) {
        float lc = lcs[t];
        g_logcum[bh*L_SZ + l0 + t] = lc;
        g_cumdec[bh*L_SZ + l0 + t] = __expf(lc);
    }
    __syncthreads();
    const float lcL = lcs[CL - 1];
    if (t < CL) wq[t] = dtv[t] * __expf(lcL - lcs[t]);
    __syncthreads();
    for (int idx = t; idx < CL * HD; idx += 256) {
        int j = idx >> 6, p = idx & 63;
        float v = __half2float(g_xBCh[(size_t)(b*L_SZ + l0 + j) * CD + h*HD + p]);
        sXTw[p * HS2 + j] = __float2half_rn(v * wq[j]);
    }
    __syncthreads();

    const int wid = t >> 5, lane = t & 31;
    const int wm = wid & 1, wn = wid >> 1;
    const int r = lane >> 2, cc = lane & 3;
    const int lrow = lane & 15, lk16 = (lane >> 4) << 4;
    uint32_t aoff[2], boff[2];
    #pragma unroll
    for (int mt = 0; mt < 2; mt++)
        aoff[mt] = sb + CS_SXTW + (uint32_t)((wm*32 + mt*16 + lrow) * (HS2*2)) + (uint32_t)lk16;
    #pragma unroll
    for (int g = 0; g < 2; g++)
        boff[g] = sb + CS_SBT + (uint32_t)((wn*32 + g*16 + lrow) * (HS2*2)) + (uint32_t)lk16;

    float acc[2][4][4];
    #pragma unroll
    for (int i = 0; i < 2; i++)
        #pragma unroll
        for (int j = 0; j < 4; j++)
            #pragma unroll
            for (int q = 0; q < 4; q++) acc[i][j][q] = 0.f;

    #pragma unroll
    for (int kb = 0; kb < 8; kb++) {
        const uint32_t koff = (uint32_t)(kb << 5);
        uint32_t ah[2][4], bhf[4][2];
        #pragma unroll
        for (int mt = 0; mt < 2; mt++)
            LDSM4(ah[mt][0], ah[mt][1], ah[mt][2], ah[mt][3], aoff[mt] + koff);
        #pragma unroll
        for (int g = 0; g < 2; g++) {
            uint32_t r0, r1, r2, r3;
            LDSM4(r0, r1, r2, r3, boff[g] + koff);
            bhf[2*g][0] = r0; bhf[2*g+1][0] = r1; bhf[2*g][1] = r2; bhf[2*g+1][1] = r3;
        }
        #pragma unroll
        for (int mt = 0; mt < 2; mt++)
            #pragma unroll
            for (int nt = 0; nt < 4; nt++) {
                float* d = acc[mt][nt];
                mma16(d[0], d[1], d[2], d[3],
                      ah[mt][0], ah[mt][1], ah[mt][2], ah[mt][3], bhf[nt][0], bhf[nt][1]);
            }
    }
    const size_t sbase = ((size_t)bh * NC + c) * (HD * DS);
    #pragma unroll
    for (int mt = 0; mt < 2; mt++) {
        const int p0 = wm*32 + mt*16 + r;
        #pragma unroll
        for (int nt = 0; nt < 4; nt++) {
            const int n0 = wn*32 + nt*8 + 2*cc;
            *(half2*)&g_SfinalH[sbase + (size_t)p0 * DS + n0] =
                __halves2half2(__float2half_rn(acc[mt][nt][0]), __float2half_rn(acc[mt][nt][1]));
            *(half2*)&g_SfinalH[sbase + (size_t)(p0+8) * DS + n0] =
                __halves2half2(__float2half_rn(acc[mt][nt][2]), __float2half_rn(acc[mt][nt][3]));
        }
    }
}

// ---------------- phase B: sequential chunk-state combine (fp32 accum) -------
__global__ void phaseB_kernel()
{
    const int bh = blockIdx.x;
    const int e0 = blockIdx.y * 1024;
    const int t  = threadIdx.x;
    __shared__ float Ps[NC];
    if (t < NC) Ps[t] = g_cumdec[bh*L_SZ + t*CL + CL - 1];
    __syncthreads();
    for (int e = e0 + t; e < e0 + 1024; e += 256) {
        float hv = 0.f;
        for (int c = 0; c < NC; c++) {
            const size_t o = ((size_t)bh * NC + c) * (HD * DS) + e;
            g_HinitH[o] = __float2half_rn(hv);
            hv = fmaf(Ps[c], hv, __half2float(g_SfinalH[o]));
        }
    }
}

// ================ chunk_out: Y = (CB^T o M o dt) @ X + cum*(C@H^T) + D*x =====
#define CO_SC   0
#define CO_SB   (128*HS2*2)                 // 34816
#define CO_SXT  (2*128*HS2*2)               // 69632
#define CO_SH   (CO_SXT + 64*HS2*2)         // 87040
#define CO_LC   (CO_SH + 64*HS2*2)          // 104448
#define CO_DT   (CO_LC + 512)
#define CO_SMEM (CO_DT + 512)               // 105472
__global__ void __launch_bounds__(256, 2) chunk_out_kernel(const float* __restrict__ Dvec)
{
    extern __shared__ __align__(16) char sm[];
    __half* sC  = (__half*)(sm + CO_SC);
    __half* sB  = (__half*)(sm + CO_SB);    // becomes sW after G
    __half* sXT = (__half*)(sm + CO_SXT);
    __half* sH  = (__half*)(sm + CO_SH);
    float*  lc  = (float*)(sm + CO_LC);
    float*  dtw = (float*)(sm + CO_DT);
    const uint32_t sb = (uint32_t)__cvta_generic_to_shared(sm);

    const int c = blockIdx.x, h = blockIdx.y, b = blockIdx.z;
    const int t = threadIdx.x;
    const int l0 = c * CL;
    const int bh = b * NH + h;
    const bool do_corr = (c != 0);

    for (int idx = t; idx < CL * 16; idx += 256) {
        int l = idx >> 4, q = idx & 15;
        const __half* base = g_xBCh + (size_t)(b*L_SZ + l0 + l) * CD;
        *(uint4*)&sC[l * HS2 + q * 8] = *(const uint4*)&base[DI + DS + q * 8];
        *(uint4*)&sB[l * HS2 + q * 8] = *(const uint4*)&base[DI + q * 8];
    }
    for (int idx = t; idx < CL * HD; idx += 256) {
        int l = idx >> 6, p = idx & 63;
        sXT[p * HS2 + l] = g_xBCh[(size_t)(b*L_SZ + l0 + l) * CD + h*HD + p];
    }
    const size_t hbase = ((size_t)bh * NC + c) * (HD * DS);
    if (do_corr) {
        for (int idx = t; idx < HD * 16; idx += 256) {
            int p = idx >> 4, q = idx & 15;
            *(uint4*)&sH[p * HS2 + q * 8] = *(const uint4*)&g_HinitH[hbase + (size_t)p * DS + q * 8];
        }
    } else {
        uint4 z = make_uint4(0, 0, 0, 0);
        for (int idx = t; idx < HD * 16; idx += 256) {
            int p = idx >> 4, q = idx & 15;
            *(uint4*)&sH[p * HS2 + q * 8] = z;
        }
    }
    if (t < CL) {
        lc[t]  = g_logcum[bh*L_SZ + l0 + t];
        dtw[t] = g_dt[(b*L_SZ + l0 + t) * NH + h];
    }
    __syncthreads();

    const int wid = t >> 5, lane = t & 31;
    const int wm = wid & 3;
    const int wn = wid >> 2;
    const int r = lane >> 2, cc = lane & 3;
    const int lrow = lane & 15, lk16 = (lane >> 4) << 4;

    uint32_t aoffC[2], aoffW[2], boffB[4], boffX[2], boffH[2];
    #pragma unroll
    for (int mt = 0; mt < 2; mt++) {
        uint32_t ro = (uint32_t)((wm*32 + mt*16 + lrow) * (HS2*2)) + (uint32_t)lk16;
        aoffC[mt] = sb + CO_SC + ro;
        aoffW[mt] = sb + CO_SB + ro;
    }
    #pragma unroll
    for (int g = 0; g < 4; g++)
        boffB[g] = sb + CO_SB + (uint32_t)((wn*64 + g*16 + lrow) * (HS2*2)) + (uint32_t)lk16;
    #pragma unroll
    for (int g = 0; g < 2; g++) {
        uint32_t ro = (uint32_t)((wn*32 + g*16 + lrow) * (HS2*2)) + (uint32_t)lk16;
        boffX[g] = sb + CO_SXT + ro;
        boffH[g] = sb + CO_SH + ro;
    }

    // ---- G = C @ B^T
    float G[2][8][4];
    #pragma unroll
    for (int i = 0; i < 2; i++)
        #pragma unroll
        for (int j = 0; j < 8; j++)
            #pragma unroll
            for (int q = 0; q < 4; q++) G[i][j][q] = 0.f;
    #pragma unroll
    for (int kb = 0; kb < 8; kb++) {
        const uint32_t koff = (uint32_t)(kb << 5);
        uint32_t ah[2][4], bhf[8][2];
        #pragma unroll
        for (int mt = 0; mt < 2; mt++)
            LDSM4(ah[mt][0], ah[mt][1], ah[mt][2], ah[mt][3], aoffC[mt] + koff);
        #pragma unroll
        for (int g = 0; g < 4; g++) {
            uint32_t r0, r1, r2, r3;
            LDSM4(r0, r1, r2, r3, boffB[g] + koff);
            bhf[2*g][0] = r0; bhf[2*g+1][0] = r1; bhf[2*g][1] = r2; bhf[2*g+1][1] = r3;
        }
        #pragma unroll
        for (int mt = 0; mt < 2; mt++)
            #pragma unroll
            for (int nt = 0; nt < 8; nt++) {
                float* d = G[mt][nt];
                mma16(d[0], d[1], d[2], d[3],
                      ah[mt][0], ah[mt][1], ah[mt][2], ah[mt][3], bhf[nt][0], bhf[nt][1]);
            }
    }
    __syncthreads();

    // ---- W[l][j] = G * dt_j * exp(lc_l - lc_j), causal
    __half* sW = sB;
    #pragma unroll
    for (int mt = 0; mt < 2; mt++) {
        const int lr0 = wm*32 + mt*16 + r;
        const int lr1 = lr0 + 8;
        const float lc0 = lc[lr0], lc1 = lc[lr1];
        #pragma unroll
        for (int nt = 0; nt < 8; nt++) {
            const int j0 = wn*64 + nt*8 + 2*cc;
            const int j1 = j0 + 1;
            const float dj0 = dtw[j0], dj1 = dtw[j1];
            const float lj0 = lc[j0], lj1 = lc[j1];
            float w00 = (j0 <= lr0) ? G[mt][nt][0] * dj0 * __expf(lc0 - lj0) : 0.f;
            float w01 = (j1 <= lr0) ? G[mt][nt][1] * dj1 * __expf(lc0 - lj1) : 0.f;
            float w10 = (j0 <= lr1) ? G[mt][nt][2] * dj0 * __expf(lc1 - lj0) : 0.f;
            float w11 = (j1 <= lr1) ? G[mt][nt][3] * dj1 * __expf(lc1 - lj1) : 0.f;
            *(half2*)&sW[lr0 * HS2 + j0] = __halves2half2(__float2half_rn(w00), __float2half_rn(w01));
            *(half2*)&sW[lr1 * HS2 + j0] = __halves2half2(__float2half_rn(w10), __float2half_rn(w11));
        }
    }
    __syncthreads();

    // ---- Y = W @ X^T ; R = C @ H^T
    float Y[2][4][4], R[2][4][4];
    #pragma unroll
    for (int i = 0; i < 2; i++)
        #pragma unroll
        for (int j = 0; j < 4; j++)
            #pragma unroll
            for (int q = 0; q < 4; q++) { Y[i][j][q] = 0.f; R[i][j][q] = 0.f; }
    #pragma unroll
    for (int kb = 0; kb < 8; kb++) {
        const uint32_t koff = (uint32_t)(kb << 5);
        uint32_t ah[2][4], bhf[4][2];
        #pragma unroll
        for (int mt = 0; mt < 2; mt++)
            LDSM4(ah[mt][0], ah[mt][1], ah[mt][2], ah[mt][3], aoffW[mt] + koff);
        #pragma unroll
        for (int g = 0; g < 2; g++) {
            uint32_t r0, r1, r2, r3;
            LDSM4(r0, r1, r2, r3, boffX[g] + koff);
            bhf[2*g][0] = r0; bhf[2*g+1][0] = r1; bhf[2*g][1] = r2; bhf[2*g+1][1] = r3;
        }
        #pragma unroll
        for (int mt = 0; mt < 2; mt++)
            #pragma unroll
            for (int nt = 0; nt < 4; nt++) {
                float* d = Y[mt][nt];
                mma16(d[0], d[1], d[2], d[3],
                      ah[mt][0], ah[mt][1], ah[mt][2], ah[mt][3], bhf[nt][0], bhf[nt][1]);
            }
    }
    if (do_corr) {
        #pragma unroll
        for (int kb = 0; kb < 8; kb++) {
            const uint32_t koff = (uint32_t)(kb << 5);
            uint32_t ah[2][4], bhf[4][2];
            #pragma unroll
            for (int mt = 0; mt < 2; mt++)
                LDSM4(ah[mt][0], ah[mt][1], ah[mt][2], ah[mt][3], aoffC[mt] + koff);
            #pragma unroll
            for (int g = 0; g < 2; g++) {
                uint32_t r0, r1, r2, r3;
                LDSM4(r0, r1, r2, r3, boffH[g] + koff);
                bhf[2*g][0] = r0; bhf[2*g+1][0] = r1; bhf[2*g][1] = r2; bhf[2*g+1][1] = r3;
            }
            #pragma unroll
            for (int mt = 0; mt < 2; mt++)
                #pragma unroll
                for (int nt = 0; nt < 4; nt++) {
                    float* d = R[mt][nt];
                    mma16(d[0], d[1], d[2], d[3],
                          ah[mt][0], ah[mt][1], ah[mt][2], ah[mt][3], bhf[nt][0], bhf[nt][1]);
                }
        }
    }

    // ---- epilogue: y = Y + exp(lc_l)*R + D*x  (fp16 out)
    const float Dh = Dvec[h];
    #pragma unroll
    for (int mt = 0; mt < 2; mt++) {
        #pragma unroll
        for (int half = 0; half < 2; half++) {
            const int lrw = wm*32 + mt*16 + r + half*8;
            const float cum = __expf(lc[lrw]);
            const size_t grow = (size_t)(b*L_SZ + l0 + lrw);
            #pragma unroll
            for (int nt = 0; nt < 4; nt++) {
                const int p0 = wn*32 + nt*8 + 2*cc;
                half2 xh = *(const half2*)&g_xBCh[grow * CD + h*HD + p0];
                float2 xv = __half22float2(xh);
                float y0 = Y[mt][nt][2*half+0] + cum * R[mt][nt][2*half+0] + Dh * xv.x;
                float y1 = Y[mt][nt][2*half+1] + cum * R[mt][nt][2*half+1] + Dh * xv.y;
                *(half2*)&g_yh[grow * DI + h*HD + p0] =
                    __halves2half2(__float2half_rn(y0), __float2half_rn(y1));
            }
        }
    }
}

// ---------------- gating (silu(z)) + RMS norm -> fp16 hi ---------------------
__global__ void __launch_bounds__(256) epilogue_kernel(const float* __restrict__ norm_w)
{
    const int row = blockIdx.x;
    const int t   = threadIdx.x;
    float gv[8];
    float ss = 0.f;
    #pragma unroll
    for (int i = 0; i < 4; i++) {
        int base = (t + i * 256) * 2;
        float2 yv = __half22float2(*(const half2*)&g_yh[(size_t)row * DI + base]);
        float2 zv = __half22float2(*(const half2*)&g_zxh[(size_t)row * NGEMM2 + base]);
        float s0 = zv.x / (1.f + expf(-zv.x));
        float s1 = zv.y / (1.f + expf(-zv.y));
        float v0 = yv.x * s0, v1 = yv.y * s1;
        gv[2*i] = v0; gv[2*i+1] = v1;
        ss += v0 * v0 + v1 * v1;
    }
    __shared__ float rs[32];
    #pragma unroll
    for (int o = 16; o; o >>= 1) ss += __shfl_xor_sync(~0u, ss, o);
    if ((t & 31) == 0) rs[t >> 5] = ss;
    __syncthreads();
    if (t < 32) {
        float v = (t < 8) ? rs[t] : 0.f;
        #pragma unroll
        for (int o = 4; o; o >>= 1) v += __shfl_xor_sync(~0u, v, o);
        if (t == 0) rs[0] = v;
    }
    __syncthreads();
    float scale = rsqrtf(rs[0] / (float)DI + EPSV);
    #pragma unroll
    for (int i = 0; i < 4; i++) {
        int base = (t + i * 256) * 2;
        float v0 = gv[2*i]   * scale * norm_w[base];
        float v1 = gv[2*i+1] * scale * norm_w[base+1];
        *(half2*)&g_yhi[(size_t)row * DI + base] =
            __halves2half2(__float2half_rn(v0), __float2half_rn(v1));
    }
}

// ---------------- launch ----------------
extern "C" void kernel_launch(void* const* d_in, const int* in_sizes, int n_in,
                              void* d_out, int out_size)
{
    const float* hidden  = (const float*)d_in[0];
    const float* dte     = (const float*)d_in[1];
    const float* W_proj  = (const float*)d_in[2];
    const float* b_proj  = (const float*)d_in[3];
    const float* W_dtmod = (const float*)d_in[4];
    const float* b_dtmod = (const float*)d_in[5];
    const float* W_in    = (const float*)d_in[6];
    const float* conv_w  = (const float*)d_in[7];
    const float* conv_b  = (const float*)d_in[8];
    const float* dt_bias = (const float*)d_in[9];
    const float* A_log   = (const float*)d_in[10];
    const float* Dvec    = (const float*)d_in[11];
    const float* norm_w  = (const float*)d_in[12];
    const float* W_out   = (const float*)d_in[13];
    float* out = (float*)d_out;

    __half *p_uhi, *p_yhi, *p_hhi, *p_hlo, *p_zxh;
    __half *p_wpt_hi, *p_wit_hi, *p_wot_hi;
    cudaGetSymbolAddress((void**)&p_uhi, g_uhi);
    cudaGetSymbolAddress((void**)&p_zxh, g_zxh);
    cudaGetSymbolAddress((void**)&p_yhi, g_yhi);
    cudaGetSymbolAddress((void**)&p_hhi, g_hhi);
    cudaGetSymbolAddress((void**)&p_hlo, g_hlo);
    cudaGetSymbolAddress((void**)&p_wpt_hi, g_wpt_hi);
    cudaGetSymbolAddress((void**)&p_wit_hi, g_wit_hi);
    cudaGetSymbolAddress((void**)&p_wot_hi, g_wot_hi);

    cudaFuncSetAttribute(gemm_h2p, cudaFuncAttributeMaxDynamicSharedMemorySize, SMEM2P);
    cudaFuncSetAttribute(gemm_h1<true >, cudaFuncAttributeMaxDynamicSharedMemorySize, SMEM1P);
    cudaFuncSetAttribute(gemm_h1<false>, cudaFuncAttributeMaxDynamicSharedMemorySize, SMEM1P);
    cudaFuncSetAttribute(chunk_state_kernel, cudaFuncAttributeMaxDynamicSharedMemorySize, CS_SMEM);
    cudaFuncSetAttribute(chunk_out_kernel,   cudaFuncAttributeMaxDynamicSharedMemorySize, CO_SMEM);

    // 0) operand prep
    wd2_kernel<<<DM/8, 256>>>(W_proj, W_in, b_proj);
    split4h_kernel<<<(ROWS*DM/4 + 255)/256, 256>>>(hidden, p_hhi, p_hlo, ROWS*DM/4);
    tsplit_kernel<<<dim3(DM/32,  DM/32), dim3(32,8)>>>(W_proj, p_wpt_hi, DM, DM);
    tsplit_kernel<<<dim3(DIPPAD/32, DM/32), dim3(32,8)>>>(W_in,  p_wit_hi, DM, DIP);
    tsplit_kernel<<<dim3(DM/32,  DI/32), dim3(32,8)>>>(W_out, p_wot_hi, DI, DM);

    // 1) u = hidden @ W_proj + b_proj   (2-pass: (Ahi+Alo)@Bhi; fp16 out)
    gemm_h2p<<<dim3(DM/128, ROWS/128), 256, SMEM2P>>>(
        p_hhi, p_hlo, p_wpt_hi, b_proj, p_uhi, ROWS, DM, DM);

    // 2) zxbcdt[:, :4352] = u @ W_in   (1-pass, fp16 output)
    gemm_h1<true><<<dim3(NGEMM2/128, ROWS/128), 256, SMEM1P>>>(
        p_uhi, p_wit_hi, nullptr, p_zxh, ROWS, NGEMM2, DM);

    // 3) dt exact from hidden via precomputed Wd2 (independent of GEMM1)
    dt_kernel<<<ROWS/8, 256>>>(hidden, dte, W_dtmod, b_dtmod, dt_bias, A_log);

    // 4) conv + silu (fp16 in/out)
    conv_kernel<<<(ROWS*CD + 255)/256, 256>>>(conv_w, conv_b);

    // 5) chunked scan in matmul form (tensor-core; fp16 state)
    chunk_state_kernel<<<dim3(NC, NH, B_SZ), 256, CS_SMEM>>>();
    phaseB_kernel<<<dim3(B_SZ*NH, 8), 256>>>();
    chunk_out_kernel<<<dim3(NC, NH, B_SZ), 256, CO_SMEM>>>(Dvec);

    // 6) gating + RMS norm
    epilogue_kernel<<<ROWS, 256>>>(norm_w);

    // 7) out = yn @ W_out   (1-pass, fp32 output)
    gemm_h1<false><<<dim3(DM/128, ROWS/128), 256, SMEM1P>>>(
        p_yhi, p_wot_hi, out, nullptr, ROWS, DM, DI);
}

// round 13
// speedup vs baseline: 1.0788x; 1.0788x over previous
#include <cuda_runtime.h>
#include <cuda_fp16.h>
#include <cuda_bf16.h>
#include <cstdint>

// ---------------- problem constants ----------------
#define B_SZ   2
#define L_SZ   2048
#define DM     1024      // d_model
#define DI     2048      // d_inner
#define DS     128       // d_state
#define DCONV  4
#define NH     32        // nheads
#define HD     64        // headdim
#define DTIME  64
#define CD     (DI + 2*DS)            // 2304 conv dim
#define DIP    (2*DI + 2*DS + NH)     // 4384 in-proj dim
#define DIPPAD 4480                   // 35*128
#define NGEMM2 4352                   // 34*128 = DI+CD (z,xBC cols only)
#define ROWS   (B_SZ*L_SZ)            // 4096
#define NC     16                     // scan chunks
#define CL     (L_SZ/NC)              // 128 chunk len
#define EPSV   1e-5f

// ---------------- scratch (device globals; no allocs allowed) ----------------
__device__ __half g_uhi[ROWS*DM], g_ulo[ROWS*DM];
__device__ __half g_zxh[ROWS*NGEMM2];      // GEMM2 output (z + xBC pre-conv), fp16
__device__ __half g_xBCh[ROWS*CD];         // conv+silu output, fp16
__device__ float  g_dt[ROWS*NH];
__device__ float  g_dtA[ROWS*NH];
__device__ float  g_cumdec[B_SZ*NH*L_SZ];
__device__ float  g_logcum[B_SZ*NH*L_SZ];
__device__ __half g_SfinalH[B_SZ*NH*NC*HD*DS];
__device__ __half g_HinitH [B_SZ*NH*NC*HD*DS];
__device__ __half g_yh[ROWS*DI];
__device__ __half g_yhi[ROWS*DI];
__device__ __half g_hhi[ROWS*DM], g_hlo[ROWS*DM];
__device__ __half g_wpt_hi[DM*DM], g_wpt_lo[DM*DM];   // W_proj^T  [1024][1024]
__device__ __half g_wit_hi[DIPPAD*DM];                // W_in^T    [4480][1024] (hi only)
__device__ __half g_wot_hi[DM*DI];                    // W_out^T   [1024][2048] (hi only)

// ---------------- mma / ldmatrix helpers ----------------
__device__ __forceinline__ void mma16(float& d0, float& d1, float& d2, float& d3,
                                      uint32_t a0, uint32_t a1, uint32_t a2, uint32_t a3,
                                      uint32_t b0, uint32_t b1)
{
    asm volatile("mma.sync.aligned.m16n8k16.row.col.f32.f16.f16.f32 "
        "{%0,%1,%2,%3},{%4,%5,%6,%7},{%8,%9},{%0,%1,%2,%3};"
        : "+f"(d0), "+f"(d1), "+f"(d2), "+f"(d3)
        : "r"(a0), "r"(a1), "r"(a2), "r"(a3), "r"(b0), "r"(b1));
}
#define LDSM4(r0,r1,r2,r3, addr) \
    asm volatile("ldmatrix.sync.aligned.m8n8.x4.shared.b16 {%0,%1,%2,%3}, [%4];" \
        : "=r"(r0), "=r"(r1), "=r"(r2), "=r"(r3) : "r"(addr))

// smem geometry (GEMMs): rows of 64 halfs padded to 72 (144B stride)
#define HSTRIDE 72
#define TBYTES  (128 * HSTRIDE * 2)       // 18432 bytes per tensor per stage
#define STAGEB3 (4 * TBYTES)
#define SMEM3P  (2 * STAGEB3)             // 147456
#define STAGEB1 (2 * TBYTES)
#define SMEM1P  (2 * STAGEB1)             // 73728 -> 2 CTAs/SM

// scan-tile smem geometry: rows of 128 halfs padded to 136
#define HS2 136

// ============ 3-pass split-FP16 GEMM (GEMM1 only) ============================
__global__ void __launch_bounds__(512, 1) gemm_h3(
    const __half* __restrict__ Ahi, const __half* __restrict__ Alo,
    const __half* __restrict__ Bhi, const __half* __restrict__ Blo,
    const float* __restrict__ bias,
    __half* __restrict__ Hout, __half* __restrict__ Lout,
    int M, int Nreal, int K)
{
    extern __shared__ __align__(16) char smem[];
    const uint32_t sb = (uint32_t)__cvta_generic_to_shared(smem);
    const int tid = threadIdx.x;
    const int wid = tid >> 5;
    const int lane = tid & 31;
    const int wm = wid & 3;
    const int wn = wid >> 2;
    const int r = lane >> 2;
    const int c = lane & 3;
    const int m0 = blockIdx.y << 7;
    const int n0 = blockIdx.x << 7;
    const int nsteps = K >> 6;

    const int t4   = tid >> 7;
    const int l128 = tid & 127;
    const __half* gsel = (t4 == 0) ? Ahi : (t4 == 1) ? Alo : (t4 == 2) ? Bhi : Blo;
    const int rb = (t4 < 2) ? m0 : n0;

    auto load_stage = [&](int kstep, int s) {
        const int k0 = kstep << 6;
        const __half* gb = gsel + (size_t)rb * K + k0;
        const uint32_t tb = sb + (uint32_t)(s * STAGEB3 + t4 * TBYTES);
        #pragma unroll
        for (int j = 0; j < 8; j++) {
            int q = j * 128 + l128;
            int row = q >> 3, col = q & 7;
            const __half* gp = gb + (size_t)row * K + (col << 3);
            uint32_t sa = tb + (uint32_t)(row * (HSTRIDE * 2) + (col << 4));
            asm volatile("cp.async.cg.shared.global [%0], [%1], 16;" :: "r"(sa), "l"(gp) : "memory");
        }
        asm volatile("cp.async.commit_group;" ::: "memory");
    };

    float acc[2][4][4];
    #pragma unroll
    for (int i = 0; i < 2; i++)
        #pragma unroll
        for (int j = 0; j < 4; j++)
            #pragma unroll
            for (int q = 0; q < 4; q++) acc[i][j][q] = 0.f;

    const int lrow = lane & 15;
    const int lk16 = (lane >> 4) << 4;
    uint32_t arow_off[2], brow_off[2];
    #pragma unroll
    for (int mt = 0; mt < 2; mt++)
        arow_off[mt] = (uint32_t)((wm * 32 + mt * 16 + lrow) * (HSTRIDE * 2)) + (uint32_t)lk16;
    #pragma unroll
    for (int g = 0; g < 2; g++)
        brow_off[g] = (uint32_t)((wn * 32 + g * 16 + lrow) * (HSTRIDE * 2)) + (uint32_t)lk16;

    load_stage(0, 0);

    for (int i = 0; i < nsteps; i++) {
        if (i + 1 < nsteps) {
            load_stage(i + 1, (i + 1) & 1);
            asm volatile("cp.async.wait_group 1;" ::: "memory");
        } else {
            asm volatile("cp.async.wait_group 0;" ::: "memory");
        }
        __syncthreads();

        const int s = i & 1;
        const uint32_t stA_hi = sb + (uint32_t)(s * STAGEB3);
        const uint32_t stA_lo = stA_hi + TBYTES;
        const uint32_t stB_hi = stA_hi + 2 * TBYTES;
        const uint32_t stB_lo = stA_hi + 3 * TBYTES;

        #pragma unroll
        for (int kb = 0; kb < 4; kb++) {
            const uint32_t koff = (uint32_t)(kb << 5);
            uint32_t ah[2][4], al[2][4], bh[4][2], bl[4][2];
            #pragma unroll
            for (int mt = 0; mt < 2; mt++) {
                LDSM4(ah[mt][0], ah[mt][1], ah[mt][2], ah[mt][3], stA_hi + arow_off[mt] + koff);
                LDSM4(al[mt][0], al[mt][1], al[mt][2], al[mt][3], stA_lo + arow_off[mt] + koff);
            }
            #pragma unroll
            for (int g = 0; g < 2; g++) {
                uint32_t r0, r1, r2, r3;
                LDSM4(r0, r1, r2, r3, stB_hi + brow_off[g] + koff);
                bh[2*g][0] = r0; bh[2*g+1][0] = r1; bh[2*g][1] = r2; bh[2*g+1][1] = r3;
                LDSM4(r0, r1, r2, r3, stB_lo + brow_off[g] + koff);
                bl[2*g][0] = r0; bl[2*g+1][0] = r1; bl[2*g][1] = r2; bl[2*g+1][1] = r3;
            }
            #pragma unroll
            for (int mt = 0; mt < 2; mt++)
                #pragma unroll
                for (int nt = 0; nt < 4; nt++) {
                    float* d = acc[mt][nt];
                    mma16(d[0], d[1], d[2], d[3],
                          ah[mt][0], ah[mt][1], ah[mt][2], ah[mt][3], bh[nt][0], bh[nt][1]);
                    mma16(d[0], d[1], d[2], d[3],
                          al[mt][0], al[mt][1], al[mt][2], al[mt][3], bh[nt][0], bh[nt][1]);
                    mma16(d[0], d[1], d[2], d[3],
                          ah[mt][0], ah[mt][1], ah[mt][2], ah[mt][3], bl[nt][0], bl[nt][1]);
                }
        }
        __syncthreads();
    }

    #pragma unroll
    for (int mt = 0; mt < 2; mt++) {
        const int row = m0 + wm * 32 + mt * 16 + r;
        #pragma unroll
        for (int nt = 0; nt < 4; nt++) {
            const int col = n0 + wn * 32 + nt * 8 + 2 * c;
            if (col < Nreal) {
                float v0 = acc[mt][nt][0] + bias[col], v1 = acc[mt][nt][1] + bias[col+1];
                float v2 = acc[mt][nt][2] + bias[col], v3 = acc[mt][nt][3] + bias[col+1];
                __half h0 = __float2half_rn(v0), h1 = __float2half_rn(v1);
                __half h2 = __float2half_rn(v2), h3 = __float2half_rn(v3);
                *(half2*)&Hout[(size_t)row * Nreal + col]       = __halves2half2(h0, h1);
                *(half2*)&Hout[(size_t)(row + 8) * Nreal + col] = __halves2half2(h2, h3);
                *(half2*)&Lout[(size_t)row * Nreal + col] =
                    __halves2half2(__float2half_rn(v0 - __half2float(h0)),
                                   __float2half_rn(v1 - __half2float(h1)));
                *(half2*)&Lout[(size_t)(row + 8) * Nreal + col] =
                    __halves2half2(__float2half_rn(v2 - __half2float(h2)),
                                   __float2half_rn(v3 - __half2float(h3)));
            }
        }
    }
}

// ============ 1-pass FP16 GEMM (GEMM2/3; 2 tensors, 2 CTAs/SM) ===============
template<bool HOUT>
__global__ void __launch_bounds__(256, 2) gemm_h1(
    const __half* __restrict__ Ahi, const __half* __restrict__ Bhi,
    float* __restrict__ Cout, __half* __restrict__ HoutP,
    int M, int Nreal, int K)
{
    extern __shared__ __align__(16) char smem[];
    const uint32_t sb = (uint32_t)__cvta_generic_to_shared(smem);
    const int tid = threadIdx.x;
    const int wid = tid >> 5;
    const int lane = tid & 31;
    const int wm = wid & 1;
    const int wn = wid >> 1;
    const int r = lane >> 2;
    const int c = lane & 3;
    const int m0 = blockIdx.y << 7;
    const int n0 = blockIdx.x << 7;
    const int nsteps = K >> 6;

    auto load_stage = [&](int kstep, int s) {
        const int k0 = kstep << 6;
        #pragma unroll
        for (int j = 0; j < 8; j++) {
            const int t = j >> 2;
            const __half* gsel = (t == 0) ? Ahi : Bhi;
            const int rb = (t == 0) ? m0 : n0;
            int rem = ((j & 3) << 8) + tid;
            int row = rem >> 3, col = rem & 7;
            const __half* gp = gsel + (size_t)(rb + row) * K + k0 + (col << 3);
            uint32_t sa = sb + (uint32_t)(s * STAGEB1 + t * TBYTES + row * (HSTRIDE * 2) + (col << 4));
            asm volatile("cp.async.cg.shared.global [%0], [%1], 16;" :: "r"(sa), "l"(gp) : "memory");
        }
        asm volatile("cp.async.commit_group;" ::: "memory");
    };

    float acc[4][4][4];
    #pragma unroll
    for (int i = 0; i < 4; i++)
        #pragma unroll
        for (int j = 0; j < 4; j++)
            #pragma unroll
            for (int q = 0; q < 4; q++) acc[i][j][q] = 0.f;

    const int lrow = lane & 15;
    const int lk16 = (lane >> 4) << 4;
    uint32_t arow_off[4], brow_off[2];
    #pragma unroll
    for (int mt = 0; mt < 4; mt++)
        arow_off[mt] = (uint32_t)((wm * 64 + mt * 16 + lrow) * (HSTRIDE * 2)) + (uint32_t)lk16;
    #pragma unroll
    for (int g = 0; g < 2; g++)
        brow_off[g] = (uint32_t)((wn * 32 + g * 16 + lrow) * (HSTRIDE * 2)) + (uint32_t)lk16;

    load_stage(0, 0);

    for (int i = 0; i < nsteps; i++) {
        if (i + 1 < nsteps) {
            load_stage(i + 1, (i + 1) & 1);
            asm volatile("cp.async.wait_group 1;" ::: "memory");
        } else {
            asm volatile("cp.async.wait_group 0;" ::: "memory");
        }
        __syncthreads();

        const int s = i & 1;
        const uint32_t stA = sb + (uint32_t)(s * STAGEB1);
        const uint32_t stB = stA + TBYTES;

        #pragma unroll
        for (int kb = 0; kb < 4; kb++) {
            const uint32_t koff = (uint32_t)(kb << 5);
            uint32_t ah[4][4], bh[4][2];
            #pragma unroll
            for (int mt = 0; mt < 4; mt++)
                LDSM4(ah[mt][0], ah[mt][1], ah[mt][2], ah[mt][3], stA + arow_off[mt] + koff);
            #pragma unroll
            for (int g = 0; g < 2; g++) {
                uint32_t r0, r1, r2, r3;
                LDSM4(r0, r1, r2, r3, stB + brow_off[g] + koff);
                bh[2*g][0] = r0; bh[2*g+1][0] = r1; bh[2*g][1] = r2; bh[2*g+1][1] = r3;
            }
            #pragma unroll
            for (int mt = 0; mt < 4; mt++)
                #pragma unroll
                for (int nt = 0; nt < 4; nt++) {
                    float* d = acc[mt][nt];
                    mma16(d[0], d[1], d[2], d[3],
                          ah[mt][0], ah[mt][1], ah[mt][2], ah[mt][3], bh[nt][0], bh[nt][1]);
                }
        }
        __syncthreads();
    }

    #pragma unroll
    for (int mt = 0; mt < 4; mt++) {
        const int row = m0 + wm * 64 + mt * 16 + r;
        #pragma unroll
        for (int nt = 0; nt < 4; nt++) {
            const int col = n0 + wn * 32 + nt * 8 + 2 * c;
            if (col < Nreal) {
                if (HOUT) {
                    *(half2*)&HoutP[(size_t)row * Nreal + col] =
                        __halves2half2(__float2half_rn(acc[mt][nt][0]), __float2half_rn(acc[mt][nt][1]));
                    *(half2*)&HoutP[(size_t)(row + 8) * Nreal + col] =
                        __halves2half2(__float2half_rn(acc[mt][nt][2]), __float2half_rn(acc[mt][nt][3]));
                } else {
                    *(float2*)&Cout[(size_t)row * Nreal + col] =
                        make_float2(acc[mt][nt][0], acc[mt][nt][1]);
                    *(float2*)&Cout[(size_t)(row + 8) * Nreal + col] =
                        make_float2(acc[mt][nt][2], acc[mt][nt][3]);
                }
            }
        }
    }
}

// ---------------- elementwise split: float -> (hi, lo) fp16 pair -------------
__global__ void split4h_kernel(const float* __restrict__ x,
                               __half* __restrict__ hi, __half* __restrict__ lo, int n4)
{
    int i = blockIdx.x * blockDim.x + threadIdx.x;
    if (i >= n4) return;
    float4 v = ((const float4*)x)[i];
    __half h0 = __float2half_rn(v.x), h1 = __float2half_rn(v.y);
    __half h2 = __float2half_rn(v.z), h3 = __float2half_rn(v.w);
    ((half2*)hi)[2*i]   = __halves2half2(h0, h1);
    ((half2*)hi)[2*i+1] = __halves2half2(h2, h3);
    ((half2*)lo)[2*i]   = __halves2half2(__float2half_rn(v.x - __half2float(h0)),
                                         __float2half_rn(v.y - __half2float(h1)));
    ((half2*)lo)[2*i+1] = __halves2half2(__float2half_rn(v.z - __half2float(h2)),
                                         __float2half_rn(v.w - __half2float(h3)));
}

// ---------------- transpose + split: W[K,N] -> Wt_hi(/lo)[Npad,K] fp16 -------
template<bool WLO>
__global__ void tsplit_kernel(const float* __restrict__ W,
                              __half* __restrict__ Thi, __half* __restrict__ Tlo,
                              int K, int N)
{
    __shared__ float t[32][33];
    const int n0 = blockIdx.x * 32, k0 = blockIdx.y * 32;
    const int tx = threadIdx.x, ty = threadIdx.y;
    #pragma unroll
    for (int r = 0; r < 4; r++) {
        int k = k0 + ty + r * 8, n = n0 + tx;
        t[ty + r * 8][tx] = (n < N) ? W[(size_t)k * N + n] : 0.f;
    }
    __syncthreads();
    #pragma unroll
    for (int r = 0; r < 4; r++) {
        int n = n0 + ty + r * 8, k = k0 + tx;
        float v = t[tx][ty + r * 8];
        __half h = __float2half_rn(v);
        Thi[(size_t)n * K + k] = h;
        if (WLO) Tlo[(size_t)n * K + k] = __float2half_rn(v - __half2float(h));
    }
}

// ---------------- dt: exact fp32 dt_raw + dtmod + softplus; stores dt, dt*A --
__global__ void __launch_bounds__(256) dt_kernel(
    const float* __restrict__ dte, const float* __restrict__ Wd,
    const float* __restrict__ bd,  const float* __restrict__ W_in,
    const float* __restrict__ dt_bias, const float* __restrict__ A_log)
{
    __shared__ float us[8][1024];
    const int row0 = blockIdx.x * 8;
    const int tid = threadIdx.x;
    for (int idx = tid; idx < 8 * 1024; idx += 256) {
        int r = idx >> 10, j = idx & 1023;
        us[r][j] = __half2float(g_uhi[(size_t)(row0 + r) * DM + j])
                 + __half2float(g_ulo[(size_t)(row0 + r) * DM + j]);
    }
    __syncthreads();
    const int r = tid >> 5, h = tid & 31;
    const int row = row0 + r;
    float s = bd[h];
    #pragma unroll 8
    for (int j = 0; j < DTIME; j++) s = fmaf(dte[(size_t)row * DTIME + j], Wd[j * NH + h], s);
    const float* wcol = W_in + (DI + CD) + h;
    float x0 = 0.f, x1 = 0.f, x2 = 0.f, x3 = 0.f;
    #pragma unroll 4
    for (int j = 0; j < DM; j += 4) {
        x0 = fmaf(us[r][j+0], wcol[(size_t)(j+0) * DIP], x0);
        x1 = fmaf(us[r][j+1], wcol[(size_t)(j+1) * DIP], x1);
        x2 = fmaf(us[r][j+2], wcol[(size_t)(j+2) * DIP], x2);
        x3 = fmaf(us[r][j+3], wcol[(size_t)(j+3) * DIP], x3);
    }
    float x = (x0 + x1) + (x2 + x3) + dt_bias[h] + s;
    float dt = (x > 20.f) ? x : log1pf(expf(x));
    float A  = -expf(A_log[h]);
    const int idx = row * NH + h;
    g_dt[idx]  = dt;
    g_dtA[idx] = dt * A;
}

// ---------------- causal conv (taps=4) + bias + silu; fp16 in/out ------------
__global__ void conv_kernel(const float* __restrict__ conv_w,
                            const float* __restrict__ conv_b)
{
    int idx = blockIdx.x * blockDim.x + threadIdx.x;
    if (idx >= ROWS * CD) return;
    int c   = idx % CD;
    int row = idx / CD;
    int l   = row & (L_SZ - 1);
    int b   = row / L_SZ;
    float acc = conv_b[c];
    #pragma unroll
    for (int k = 0; k < DCONV; k++) {
        int ll = l - (DCONV - 1) + k;
        if (ll >= 0)
            acc = fmaf(__half2float(g_zxh[(size_t)(b*L_SZ + ll) * NGEMM2 + DI + c]),
                       conv_w[k*CD + c], acc);
    }
    g_xBCh[idx] = __float2half_rn(acc / (1.f + expf(-acc)));
}

// ================= chunk_state: logcum/cumdec + Sfinal = Xw^T @ B ===========
#define CS_SXTW 0
#define CS_SBT  (64*HS2*2)                 // 17408
#define CS_LCS  (CS_SBT + 128*HS2*2)       // 52224
#define CS_DTV  (CS_LCS + 512)
#define CS_WQ   (CS_DTV + 512)
#define CS_SMEM (CS_WQ + 512)              // 53760
__global__ void __launch_bounds__(256, 2) chunk_state_kernel()
{
    extern __shared__ __align__(16) char sm[];
    __half* sXTw = (__half*)(sm + CS_SXTW);
    __half* sBT  = (__half*)(sm + CS_SBT);
    float*  lcs  = (float*)(sm + CS_LCS);
    float*  dtv  = (float*)(sm + CS_DTV);
    float*  wq   = (float*)(sm + CS_WQ);
    const uint32_t sb = (uint32_t)__cvta_generic_to_shared(sm);

    const int c = blockIdx.x, h = blockIdx.y, b = blockIdx.z;
    const int t = threadIdx.x;
    const int l0 = c * CL;
    const int bh = b * NH + h;

    for (int idx = t; idx < CL * DS; idx += 256) {
        int j = idx >> 7, n = idx & 127;
        sBT[n * HS2 + j] = g_xBCh[(size_t)(b*L_SZ + l0 + j) * CD + DI + n];
    }
    if (t < CL) {
        dtv[t] = g_dt [(b*L_SZ + l0 + t) * NH + h];
        lcs[t] = g_dtA[(b*L_SZ + l0 + t) * NH + h];
    }
    __syncthreads();
    for (int off = 1; off < CL; off <<= 1) {
        float cur = 0.f, v = 0.f;
        if (t < CL) { cur = lcs[t]; if (t >= off) v = lcs[t - off]; }
        __syncthreads();
        if (t < CL) lcs[t] = cur + v;
        __syncthreads();
    }
    if (t < CL) {
        float lc = lcs[t];
        g_logcum[bh*L_SZ + l0 + t] = lc;
        g_cumdec[bh*L_SZ + l0 + t] = __expf(lc);
    }
    __syncthreads();
    const float lcL = lcs[CL - 1];
    if (t < CL) wq[t] = dtv[t] * __expf(lcL - lcs[t]);
    __syncthreads();
    for (int idx = t; idx < CL * HD; idx += 256) {
        int j = idx >> 6, p = idx & 63;
        float v = __half2float(g_xBCh[(size_t)(b*L_SZ + l0 + j) * CD + h*HD + p]);
        sXTw[p * HS2 + j] = __float2half_rn(v * wq[j]);
    }
    __syncthreads();

    const int wid = t >> 5, lane = t & 31;
    const int wm = wid & 1, wn = wid >> 1;
    const int r = lane >> 2, cc = lane & 3;
    const int lrow = lane & 15, lk16 = (lane >> 4) << 4;
    uint32_t aoff[2], boff[2];
    #pragma unroll
    for (int mt = 0; mt < 2; mt++)
        aoff[mt] = sb + CS_SXTW + (uint32_t)((wm*32 + mt*16 + lrow) * (HS2*2)) + (uint32_t)lk16;
    #pragma unroll
    for (int g = 0; g < 2; g++)
        boff[g] = sb + CS_SBT + (uint32_t)((wn*32 + g*16 + lrow) * (HS2*2)) + (uint32_t)lk16;

    float acc[2][4][4];
    #pragma unroll
    for (int i = 0; i < 2; i++)
        #pragma unroll
        for (int j = 0; j < 4; j++)
            #pragma unroll
            for (int q = 0; q < 4; q++) acc[i][j][q] = 0.f;

    #pragma unroll
    for (int kb = 0; kb < 8; kb++) {
        const uint32_t koff = (uint32_t)(kb << 5);
        uint32_t ah[2][4], bhf[4][2];
        #pragma unroll
        for (int mt = 0; mt < 2; mt++)
            LDSM4(ah[mt][0], ah[mt][1], ah[mt][2], ah[mt][3], aoff[mt] + koff);
        #pragma unroll
        for (int g = 0; g < 2; g++) {
            uint32_t r0, r1, r2, r3;
            LDSM4(r0, r1, r2, r3, boff[g] + koff);
            bhf[2*g][0] = r0; bhf[2*g+1][0] = r1; bhf[2*g][1] = r2; bhf[2*g+1][1] = r3;
        }
        #pragma unroll
        for (int mt = 0; mt < 2; mt++)
            #pragma unroll
            for (int nt = 0; nt < 4; nt++) {
                float* d = acc[mt][nt];
                mma16(d[0], d[1], d[2], d[3],
                      ah[mt][0], ah[mt][1], ah[mt][2], ah[mt][3], bhf[nt][0], bhf[nt][1]);
            }
    }
    const size_t sbase = ((size_t)bh * NC + c) * (HD * DS);
    #pragma unroll
    for (int mt = 0; mt < 2; mt++) {
        const int p0 = wm*32 + mt*16 + r;
        #pragma unroll
        for (int nt = 0; nt < 4; nt++) {
            const int n0 = wn*32 + nt*8 + 2*cc;
            *(half2*)&g_SfinalH[sbase + (size_t)p0 * DS + n0] =
                __halves2half2(__float2half_rn(acc[mt][nt][0]), __float2half_rn(acc[mt][nt][1]));
            *(half2*)&g_SfinalH[sbase + (size_t)(p0+8) * DS + n0] =
                __halves2half2(__float2half_rn(acc[mt][nt][2]), __float2half_rn(acc[mt][nt][3]));
        }
    }
}

// ---------------- phase B: sequential chunk-state combine (fp32 accum) -------
__global__ void phaseB_kernel()
{
    const int bh = blockIdx.x;
    const int e0 = blockIdx.y * 1024;
    const int t  = threadIdx.x;
    __shared__ float Ps[NC];
    if (t < NC) Ps[t] = g_cumdec[bh*L_SZ + t*CL + CL - 1];
    __syncthreads();
    for (int e = e0 + t; e < e0 + 1024; e += 256) {
        float hv = 0.f;
        for (int c = 0; c < NC; c++) {
            const size_t o = ((size_t)bh * NC + c) * (HD * DS) + e;
            g_HinitH[o] = __float2half_rn(hv);
            hv = fmaf(Ps[c], hv, __half2float(g_SfinalH[o]));
        }
    }
}

// ================ chunk_out: Y = (CB^T o M o dt) @ X + cum*(C@H^T) + D*x =====
#define CO_SC   0
#define CO_SB   (128*HS2*2)                 // 34816
#define CO_SXT  (2*128*HS2*2)               // 69632
#define CO_SH   (CO_SXT + 64*HS2*2)         // 87040
#define CO_LC   (CO_SH + 64*HS2*2)          // 104448
#define CO_DT   (CO_LC + 512)
#define CO_SMEM (CO_DT + 512)               // 105472
__global__ void __launch_bounds__(256, 2) chunk_out_kernel(const float* __restrict__ Dvec)
{
    extern __shared__ __align__(16) char sm[];
    __half* sC  = (__half*)(sm + CO_SC);
    __half* sB  = (__half*)(sm + CO_SB);    // becomes sW after G
    __half* sXT = (__half*)(sm + CO_SXT);
    __half* sH  = (__half*)(sm + CO_SH);
    float*  lc  = (float*)(sm + CO_LC);
    float*  dtw = (float*)(sm + CO_DT);
    const uint32_t sb = (uint32_t)__cvta_generic_to_shared(sm);

    const int c = blockIdx.x, h = blockIdx.y, b = blockIdx.z;
    const int t = threadIdx.x;
    const int l0 = c * CL;
    const int bh = b * NH + h;
    const bool do_corr = (c != 0);

    for (int idx = t; idx < CL * 16; idx += 256) {
        int l = idx >> 4, q = idx & 15;
        const __half* base = g_xBCh + (size_t)(b*L_SZ + l0 + l) * CD;
        *(uint4*)&sC[l * HS2 + q * 8] = *(const uint4*)&base[DI + DS + q * 8];
        *(uint4*)&sB[l * HS2 + q * 8] = *(const uint4*)&base[DI + q * 8];
    }
    for (int idx = t; idx < CL * HD; idx += 256) {
        int l = idx >> 6, p = idx & 63;
        sXT[p * HS2 + l] = g_xBCh[(size_t)(b*L_SZ + l0 + l) * CD + h*HD + p];
    }
    const size_t hbase = ((size_t)bh * NC + c) * (HD * DS);
    if (do_corr) {
        for (int idx = t; idx < HD * 16; idx += 256) {
            int p = idx >> 4, q = idx & 15;
            *(uint4*)&sH[p * HS2 + q * 8] = *(const uint4*)&g_HinitH[hbase + (size_t)p * DS + q * 8];
        }
    } else {
        uint4 z = make_uint4(0, 0, 0, 0);
        for (int idx = t; idx < HD * 16; idx += 256) {
            int p = idx >> 4, q = idx & 15;
            *(uint4*)&sH[p * HS2 + q * 8] = z;
        }
    }
    if (t < CL) {
        lc[t]  = g_logcum[bh*L_SZ + l0 + t];
        dtw[t] = g_dt[(b*L_SZ + l0 + t) * NH + h];
    }
    __syncthreads();

    const int wid = t >> 5, lane = t & 31;
    const int wm = wid & 3;
    const int wn = wid >> 2;
    const int r = lane >> 2, cc = lane & 3;
    const int lrow = lane & 15, lk16 = (lane >> 4) << 4;

    uint32_t aoffC[2], aoffW[2], boffB[4], boffX[2], boffH[2];
    #pragma unroll
    for (int mt = 0; mt < 2; mt++) {
        uint32_t ro = (uint32_t)((wm*32 + mt*16 + lrow) * (HS2*2)) + (uint32_t)lk16;
        aoffC[mt] = sb + CO_SC + ro;
        aoffW[mt] = sb + CO_SB + ro;
    }
    #pragma unroll
    for (int g = 0; g < 4; g++)
        boffB[g] = sb + CO_SB + (uint32_t)((wn*64 + g*16 + lrow) * (HS2*2)) + (uint32_t)lk16;
    #pragma unroll
    for (int g = 0; g < 2; g++) {
        uint32_t ro = (uint32_t)((wn*32 + g*16 + lrow) * (HS2*2)) + (uint32_t)lk16;
        boffX[g] = sb + CO_SXT + ro;
        boffH[g] = sb + CO_SH + ro;
    }

    // ---- G = C @ B^T
    float G[2][8][4];
    #pragma unroll
    for (int i = 0; i < 2; i++)
        #pragma unroll
        for (int j = 0; j < 8; j++)
            #pragma unroll
            for (int q = 0; q < 4; q++) G[i][j][q] = 0.f;
    #pragma unroll
    for (int kb = 0; kb < 8; kb++) {
        const uint32_t koff = (uint32_t)(kb << 5);
        uint32_t ah[2][4], bhf[8][2];
        #pragma unroll
        for (int mt = 0; mt < 2; mt++)
            LDSM4(ah[mt][0], ah[mt][1], ah[mt][2], ah[mt][3], aoffC[mt] + koff);
        #pragma unroll
        for (int g = 0; g < 4; g++) {
            uint32_t r0, r1, r2, r3;
            LDSM4(r0, r1, r2, r3, boffB[g] + koff);
            bhf[2*g][0] = r0; bhf[2*g+1][0] = r1; bhf[2*g][1] = r2; bhf[2*g+1][1] = r3;
        }
        #pragma unroll
        for (int mt = 0; mt < 2; mt++)
            #pragma unroll
            for (int nt = 0; nt < 8; nt++) {
                float* d = G[mt][nt];
                mma16(d[0], d[1], d[2], d[3],
                      ah[mt][0], ah[mt][1], ah[mt][2], ah[mt][3], bhf[nt][0], bhf[nt][1]);
            }
    }
    __syncthreads();

    // ---- W[l][j] = G * dt_j * exp(lc_l - lc_j), causal
    __half* sW = sB;
    #pragma unroll
    for (int mt = 0; mt < 2; mt++) {
        const int lr0 = wm*32 + mt*16 + r;
        const int lr1 = lr0 + 8;
        const float lc0 = lc[lr0], lc1 = lc[lr1];
        #pragma unroll
        for (int nt = 0; nt < 8; nt++) {
            const int j0 = wn*64 + nt*8 + 2*cc;
            const int j1 = j0 + 1;
            const float dj0 = dtw[j0], dj1 = dtw[j1];
            const float lj0 = lc[j0], lj1 = lc[j1];
            float w00 = (j0 <= lr0) ? G[mt][nt][0] * dj0 * __expf(lc0 - lj0) : 0.f;
            float w01 = (j1 <= lr0) ? G[mt][nt][1] * dj1 * __expf(lc0 - lj1) : 0.f;
            float w10 = (j0 <= lr1) ? G[mt][nt][2] * dj0 * __expf(lc1 - lj0) : 0.f;
            float w11 = (j1 <= lr1) ? G[mt][nt][3] * dj1 * __expf(lc1 - lj1) : 0.f;
            *(half2*)&sW[lr0 * HS2 + j0] = __halves2half2(__float2half_rn(w00), __float2half_rn(w01));
            *(half2*)&sW[lr1 * HS2 + j0] = __halves2half2(__float2half_rn(w10), __float2half_rn(w11));
        }
    }
    __syncthreads();

    // ---- Y = W @ X^T ; R = C @ H^T
    float Y[2][4][4], R[2][4][4];
    #pragma unroll
    for (int i = 0; i < 2; i++)
        #pragma unroll
        for (int j = 0; j < 4; j++)
            #pragma unroll
            for (int q = 0; q < 4; q++) { Y[i][j][q] = 0.f; R[i][j][q] = 0.f; }
    #pragma unroll
    for (int kb = 0; kb < 8; kb++) {
        const uint32_t koff = (uint32_t)(kb << 5);
        uint32_t ah[2][4], bhf[4][2];
        #pragma unroll
        for (int mt = 0; mt < 2; mt++)
            LDSM4(ah[mt][0], ah[mt][1], ah[mt][2], ah[mt][3], aoffW[mt] + koff);
        #pragma unroll
        for (int g = 0; g < 2; g++) {
            uint32_t r0, r1, r2, r3;
            LDSM4(r0, r1, r2, r3, boffX[g] + koff);
            bhf[2*g][0] = r0; bhf[2*g+1][0] = r1; bhf[2*g][1] = r2; bhf[2*g+1][1] = r3;
        }
        #pragma unroll
        for (int mt = 0; mt < 2; mt++)
            #pragma unroll
            for (int nt = 0; nt < 4; nt++) {
                float* d = Y[mt][nt];
                mma16(d[0], d[1], d[2], d[3],
                      ah[mt][0], ah[mt][1], ah[mt][2], ah[mt][3], bhf[nt][0], bhf[nt][1]);
            }
    }
    if (do_corr) {
        #pragma unroll
        for (int kb = 0; kb < 8; kb++) {
            const uint32_t koff = (uint32_t)(kb << 5);
            uint32_t ah[2][4], bhf[4][2];
            #pragma unroll
            for (int mt = 0; mt < 2; mt++)
                LDSM4(ah[mt][0], ah[mt][1], ah[mt][2], ah[mt][3], aoffC[mt] + koff);
            #pragma unroll
            for (int g = 0; g < 2; g++) {
                uint32_t r0, r1, r2, r3;
                LDSM4(r0, r1, r2, r3, boffH[g] + koff);
                bhf[2*g][0] = r0; bhf[2*g+1][0] = r1; bhf[2*g][1] = r2; bhf[2*g+1][1] = r3;
            }
            #pragma unroll
            for (int mt = 0; mt < 2; mt++)
                #pragma unroll
                for (int nt = 0; nt < 4; nt++) {
                    float* d = R[mt][nt];
                    mma16(d[0], d[1], d[2], d[3],
                          ah[mt][0], ah[mt][1], ah[mt][2], ah[mt][3], bhf[nt][0], bhf[nt][1]);
                }
        }
    }

    // ---- epilogue: y = Y + exp(lc_l)*R + D*x  (fp16 out)
    const float Dh = Dvec[h];
    #pragma unroll
    for (int mt = 0; mt < 2; mt++) {
        #pragma unroll
        for (int half = 0; half < 2; half++) {
            const int lrw = wm*32 + mt*16 + r + half*8;
            const float cum = __expf(lc[lrw]);
            const size_t grow = (size_t)(b*L_SZ + l0 + lrw);
            #pragma unroll
            for (int nt = 0; nt < 4; nt++) {
                const int p0 = wn*32 + nt*8 + 2*cc;
                half2 xh = *(const half2*)&g_xBCh[grow * CD + h*HD + p0];
                float2 xv = __half22float2(xh);
                float y0 = Y[mt][nt][2*half+0] + cum * R[mt][nt][2*half+0] + Dh * xv.x;
                float y1 = Y[mt][nt][2*half+1] + cum * R[mt][nt][2*half+1] + Dh * xv.y;
                *(half2*)&g_yh[grow * DI + h*HD + p0] =
                    __halves2half2(__float2half_rn(y0), __float2half_rn(y1));
            }
        }
    }
}

// ---------------- gating (silu(z)) + RMS norm -> fp16 hi ---------------------
__global__ void __launch_bounds__(256) epilogue_kernel(const float* __restrict__ norm_w)
{
    const int row = blockIdx.x;
    const int t   = threadIdx.x;
    float gv[8];
    float ss = 0.f;
    #pragma unroll
    for (int i = 0; i < 4; i++) {
        int base = (t + i * 256) * 2;
        float2 yv = __half22float2(*(const half2*)&g_yh[(size_t)row * DI + base]);
        float2 zv = __half22float2(*(const half2*)&g_zxh[(size_t)row * NGEMM2 + base]);
        float s0 = zv.x / (1.f + expf(-zv.x));
        float s1 = zv.y / (1.f + expf(-zv.y));
        float v0 = yv.x * s0, v1 = yv.y * s1;
        gv[2*i] = v0; gv[2*i+1] = v1;
        ss += v0 * v0 + v1 * v1;
    }
    __shared__ float rs[32];
    #pragma unroll
    for (int o = 16; o; o >>= 1) ss += __shfl_xor_sync(~0u, ss, o);
    if ((t & 31) == 0) rs[t >> 5] = ss;
    __syncthreads();
    if (t < 32) {
        float v = (t < 8) ? rs[t] : 0.f;
        #pragma unroll
        for (int o = 4; o; o >>= 1) v += __shfl_xor_sync(~0u, v, o);
        if (t == 0) rs[0] = v;
    }
    __syncthreads();
    float scale = rsqrtf(rs[0] / (float)DI + EPSV);
    #pragma unroll
    for (int i = 0; i < 4; i++) {
        int base = (t + i * 256) * 2;
        float v0 = gv[2*i]   * scale * norm_w[base];
        float v1 = gv[2*i+1] * scale * norm_w[base+1];
        *(half2*)&g_yhi[(size_t)row * DI + base] =
            __halves2half2(__float2half_rn(v0), __float2half_rn(v1));
    }
}

// ---------------- launch ----------------
extern "C" void kernel_launch(void* const* d_in, const int* in_sizes, int n_in,
                              void* d_out, int out_size)
{
    const float* hidden  = (const float*)d_in[0];
    const float* dte     = (const float*)d_in[1];
    const float* W_proj  = (const float*)d_in[2];
    const float* b_proj  = (const float*)d_in[3];
    const float* W_dtmod = (const float*)d_in[4];
    const float* b_dtmod = (const float*)d_in[5];
    const float* W_in    = (const float*)d_in[6];
    const float* conv_w  = (const float*)d_in[7];
    const float* conv_b  = (const float*)d_in[8];
    const float* dt_bias = (const float*)d_in[9];
    const float* A_log   = (const float*)d_in[10];
    const float* Dvec    = (const float*)d_in[11];
    const float* norm_w  = (const float*)d_in[12];
    const float* W_out   = (const float*)d_in[13];
    float* out = (float*)d_out;

    __half *p_uhi, *p_ulo, *p_yhi, *p_hhi, *p_hlo, *p_zxh;
    __half *p_wpt_hi, *p_wpt_lo, *p_wit_hi, *p_wot_hi;
    cudaGetSymbolAddress((void**)&p_uhi, g_uhi);
    cudaGetSymbolAddress((void**)&p_ulo, g_ulo);
    cudaGetSymbolAddress((void**)&p_zxh, g_zxh);
    cudaGetSymbolAddress((void**)&p_yhi, g_yhi);
    cudaGetSymbolAddress((void**)&p_hhi, g_hhi);
    cudaGetSymbolAddress((void**)&p_hlo, g_hlo);
    cudaGetSymbolAddress((void**)&p_wpt_hi, g_wpt_hi);
    cudaGetSymbolAddress((void**)&p_wpt_lo, g_wpt_lo);
    cudaGetSymbolAddress((void**)&p_wit_hi, g_wit_hi);
    cudaGetSymbolAddress((void**)&p_wot_hi, g_wot_hi);

    cudaFuncSetAttribute(gemm_h3, cudaFuncAttributeMaxDynamicSharedMemorySize, SMEM3P);
    cudaFuncSetAttribute(gemm_h1<true >, cudaFuncAttributeMaxDynamicSharedMemorySize, SMEM1P);
    cudaFuncSetAttribute(gemm_h1<false>, cudaFuncAttributeMaxDynamicSharedMemorySize, SMEM1P);
    cudaFuncSetAttribute(chunk_state_kernel, cudaFuncAttributeMaxDynamicSharedMemorySize, CS_SMEM);
    cudaFuncSetAttribute(chunk_out_kernel,   cudaFuncAttributeMaxDynamicSharedMemorySize, CO_SMEM);

    // 0) operand prep
    split4h_kernel<<<(ROWS*DM/4 + 255)/256, 256>>>(hidden, p_hhi, p_hlo, ROWS*DM/4);
    tsplit_kernel<true ><<<dim3(DM/32,  DM/32), dim3(32,8)>>>(W_proj, p_wpt_hi, p_wpt_lo, DM, DM);
    tsplit_kernel<false><<<dim3(DIPPAD/32, DM/32), dim3(32,8)>>>(W_in,  p_wit_hi, nullptr, DM, DIP);
    tsplit_kernel<false><<<dim3(DM/32,  DI/32), dim3(32,8)>>>(W_out, p_wot_hi, nullptr, DI, DM);

    // 1) u = hidden @ W_proj + b_proj   (3-pass; split fp16 output)
    gemm_h3<<<dim3(DM/128, ROWS/128), 512, SMEM3P>>>(
        p_hhi, p_hlo, p_wpt_hi, p_wpt_lo, b_proj, p_uhi, p_ulo, ROWS, DM, DM);

    // 2) zxbcdt[:, :4352] = u @ W_in   (1-pass, fp16 output)
    gemm_h1<true><<<dim3(NGEMM2/128, ROWS/128), 256, SMEM1P>>>(
        p_uhi, p_wit_hi, nullptr, p_zxh, ROWS, NGEMM2, DM);

    // 3) dt exact (from split u against fp32 W_in column)
    dt_kernel<<<ROWS/8, 256>>>(dte, W_dtmod, b_dtmod, W_in, dt_bias, A_log);

    // 4) conv + silu (fp16 in/out)
    conv_kernel<<<(ROWS*CD + 255)/256, 256>>>(conv_w, conv_b);

    // 5) chunked scan in matmul form (tensor-core; fp16 state)
    chunk_state_kernel<<<dim3(NC, NH, B_SZ), 256, CS_SMEM>>>();
    phaseB_kernel<<<dim3(B_SZ*NH, 8), 256>>>();
    chunk_out_kernel<<<dim3(NC, NH, B_SZ), 256, CO_SMEM>>>(Dvec);

    // 6) gating + RMS norm
    epilogue_kernel<<<ROWS, 256>>>(norm_w);

    // 7) out = yn @ W_out   (1-pass, fp32 output)
    gemm_h1<false><<<dim3(DM/128, ROWS/128), 256, SMEM1P>>>(
        p_yhi, p_wot_hi, out, nullptr, ROWS, DM, DI);
}

// round 14
// speedup vs baseline: 1.0923x; 1.0125x over previous
#include <cuda_runtime.h>
#include <cuda_fp16.h>
#include <cuda_bf16.h>
#include <cstdint>

// ---------------- problem constants ----------------
#define B_SZ   2
#define L_SZ   2048
#define DM     1024      // d_model
#define DI     2048      // d_inner
#define DS     128       // d_state
#define DCONV  4
#define NH     32        // nheads
#define HD     64        // headdim
#define DTIME  64
#define CD     (DI + 2*DS)            // 2304 conv dim
#define DIP    (2*DI + 2*DS + NH)     // 4384 in-proj dim
#define DIPPAD 4480                   // 35*128
#define NGEMM2 4352                   // 34*128 = DI+CD (z,xBC cols only)
#define ROWS   (B_SZ*L_SZ)            // 4096
#define NC     16                     // scan chunks
#define CL     (L_SZ/NC)              // 128 chunk len
#define EPSV   1e-5f

// ---------------- scratch (device globals; no allocs allowed) ----------------
__device__ __half g_uhi[ROWS*DM], g_ulo[ROWS*DM];
__device__ __half g_zxh[ROWS*NGEMM2];      // GEMM2 output (z + xBC pre-conv), fp16
__device__ __half g_xBCh[ROWS*CD];         // conv+silu output, fp16
__device__ float  g_dt[ROWS*NH];
__device__ float  g_dtA[ROWS*NH];
__device__ float  g_cumdec[B_SZ*NH*L_SZ];
__device__ float  g_logcum[B_SZ*NH*L_SZ];
__device__ __half g_SfinalH[B_SZ*NH*NC*HD*DS];
__device__ __half g_HinitH [B_SZ*NH*NC*HD*DS];
__device__ __half g_yh[ROWS*DI];
__device__ __half g_yhi[ROWS*DI];
__device__ __half g_hhi[ROWS*DM], g_hlo[ROWS*DM];
__device__ __half g_wpt_hi[DM*DM], g_wpt_lo[DM*DM];   // W_proj^T  [1024][1024]
__device__ __half g_wit_hi[DIPPAD*DM];                // W_in^T    [4480][1024] (hi only)
__device__ __half g_wot_hi[DM*DI];                    // W_out^T   [1024][2048] (hi only)

// ---------------- mma / ldmatrix helpers ----------------
__device__ __forceinline__ void mma16(float& d0, float& d1, float& d2, float& d3,
                                      uint32_t a0, uint32_t a1, uint32_t a2, uint32_t a3,
                                      uint32_t b0, uint32_t b1)
{
    asm volatile("mma.sync.aligned.m16n8k16.row.col.f32.f16.f16.f32 "
        "{%0,%1,%2,%3},{%4,%5,%6,%7},{%8,%9},{%0,%1,%2,%3};"
        : "+f"(d0), "+f"(d1), "+f"(d2), "+f"(d3)
        : "r"(a0), "r"(a1), "r"(a2), "r"(a3), "r"(b0), "r"(b1));
}
#define LDSM4(r0,r1,r2,r3, addr) \
    asm volatile("ldmatrix.sync.aligned.m8n8.x4.shared.b16 {%0,%1,%2,%3}, [%4];" \
        : "=r"(r0), "=r"(r1), "=r"(r2), "=r"(r3) : "r"(addr))

// smem geometry (GEMMs): rows of 64 halfs padded to 72 (144B stride)
#define HSTRIDE 72
#define TBYTES  (128 * HSTRIDE * 2)       // 18432 bytes per tensor per stage
#define STAGEB3 (4 * TBYTES)
#define SMEM3P  (3 * STAGEB3)             // 221184 (3-stage, 1 CTA/SM)
#define STAGEB1 (2 * TBYTES)
#define SMEM1P  (3 * STAGEB1)             // 110592 (3-stage, 2 CTAs/SM)

// scan-tile smem geometry: rows of 128 halfs padded to 136
#define HS2 136

// ============ 3-pass split-FP16 GEMM (GEMM1 only; 3-stage pipeline) ==========
__global__ void __launch_bounds__(512, 1) gemm_h3(
    const __half* __restrict__ Ahi, const __half* __restrict__ Alo,
    const __half* __restrict__ Bhi, const __half* __restrict__ Blo,
    const float* __restrict__ bias,
    __half* __restrict__ Hout, __half* __restrict__ Lout,
    int M, int Nreal, int K)
{
    extern __shared__ __align__(16) char smem[];
    const uint32_t sb = (uint32_t)__cvta_generic_to_shared(smem);
    const int tid = threadIdx.x;
    const int wid = tid >> 5;
    const int lane = tid & 31;
    const int wm = wid & 3;
    const int wn = wid >> 2;
    const int r = lane >> 2;
    const int c = lane & 3;
    const int m0 = blockIdx.y << 7;
    const int n0 = blockIdx.x << 7;
    const int nsteps = K >> 6;

    const int t4   = tid >> 7;
    const int l128 = tid & 127;
    const __half* gsel = (t4 == 0) ? Ahi : (t4 == 1) ? Alo : (t4 == 2) ? Bhi : Blo;
    const int rb = (t4 < 2) ? m0 : n0;

    auto load_stage = [&](int kstep, int s) {
        const int k0 = kstep << 6;
        const __half* gb = gsel + (size_t)rb * K + k0;
        const uint32_t tb = sb + (uint32_t)(s * STAGEB3 + t4 * TBYTES);
        #pragma unroll
        for (int j = 0; j < 8; j++) {
            int q = j * 128 + l128;
            int row = q >> 3, col = q & 7;
            const __half* gp = gb + (size_t)row * K + (col << 3);
            uint32_t sa = tb + (uint32_t)(row * (HSTRIDE * 2) + (col << 4));
            asm volatile("cp.async.cg.shared.global [%0], [%1], 16;" :: "r"(sa), "l"(gp) : "memory");
        }
        asm volatile("cp.async.commit_group;" ::: "memory");
    };

    float acc[2][4][4];
    #pragma unroll
    for (int i = 0; i < 2; i++)
        #pragma unroll
        for (int j = 0; j < 4; j++)
            #pragma unroll
            for (int q = 0; q < 4; q++) acc[i][j][q] = 0.f;

    const int lrow = lane & 15;
    const int lk16 = (lane >> 4) << 4;
    uint32_t arow_off[2], brow_off[2];
    #pragma unroll
    for (int mt = 0; mt < 2; mt++)
        arow_off[mt] = (uint32_t)((wm * 32 + mt * 16 + lrow) * (HSTRIDE * 2)) + (uint32_t)lk16;
    #pragma unroll
    for (int g = 0; g < 2; g++)
        brow_off[g] = (uint32_t)((wn * 32 + g * 16 + lrow) * (HSTRIDE * 2)) + (uint32_t)lk16;

    load_stage(0, 0);
    if (nsteps > 1) load_stage(1, 1);

    for (int i = 0; i < nsteps; i++) {
        if (i + 2 < nsteps) load_stage(i + 2, (i + 2) % 3);
        const int rem = nsteps - 1 - i;
        if (rem >= 2)      asm volatile("cp.async.wait_group 2;" ::: "memory");
        else if (rem == 1) asm volatile("cp.async.wait_group 1;" ::: "memory");
        else               asm volatile("cp.async.wait_group 0;" ::: "memory");
        __syncthreads();

        const int s = i % 3;
        const uint32_t stA_hi = sb + (uint32_t)(s * STAGEB3);
        const uint32_t stA_lo = stA_hi + TBYTES;
        const uint32_t stB_hi = stA_hi + 2 * TBYTES;
        const uint32_t stB_lo = stA_hi + 3 * TBYTES;

        #pragma unroll
        for (int kb = 0; kb < 4; kb++) {
            const uint32_t koff = (uint32_t)(kb << 5);
            uint32_t ah[2][4], al[2][4], bh[4][2], bl[4][2];
            #pragma unroll
            for (int mt = 0; mt < 2; mt++) {
                LDSM4(ah[mt][0], ah[mt][1], ah[mt][2], ah[mt][3], stA_hi + arow_off[mt] + koff);
                LDSM4(al[mt][0], al[mt][1], al[mt][2], al[mt][3], stA_lo + arow_off[mt] + koff);
            }
            #pragma unroll
            for (int g = 0; g < 2; g++) {
                uint32_t r0, r1, r2, r3;
                LDSM4(r0, r1, r2, r3, stB_hi + brow_off[g] + koff);
                bh[2*g][0] = r0; bh[2*g+1][0] = r1; bh[2*g][1] = r2; bh[2*g+1][1] = r3;
                LDSM4(r0, r1, r2, r3, stB_lo + brow_off[g] + koff);
                bl[2*g][0] = r0; bl[2*g+1][0] = r1; bl[2*g][1] = r2; bl[2*g+1][1] = r3;
            }
            #pragma unroll
            for (int mt = 0; mt < 2; mt++)
                #pragma unroll
                for (int nt = 0; nt < 4; nt++) {
                    float* d = acc[mt][nt];
                    mma16(d[0], d[1], d[2], d[3],
                          ah[mt][0], ah[mt][1], ah[mt][2], ah[mt][3], bh[nt][0], bh[nt][1]);
                    mma16(d[0], d[1], d[2], d[3],
                          al[mt][0], al[mt][1], al[mt][2], al[mt][3], bh[nt][0], bh[nt][1]);
                    mma16(d[0], d[1], d[2], d[3],
                          ah[mt][0], ah[mt][1], ah[mt][2], ah[mt][3], bl[nt][0], bl[nt][1]);
                }
        }
        __syncthreads();
    }

    #pragma unroll
    for (int mt = 0; mt < 2; mt++) {
        const int row = m0 + wm * 32 + mt * 16 + r;
        #pragma unroll
        for (int nt = 0; nt < 4; nt++) {
            const int col = n0 + wn * 32 + nt * 8 + 2 * c;
            if (col < Nreal) {
                float v0 = acc[mt][nt][0] + bias[col], v1 = acc[mt][nt][1] + bias[col+1];
                float v2 = acc[mt][nt][2] + bias[col], v3 = acc[mt][nt][3] + bias[col+1];
                __half h0 = __float2half_rn(v0), h1 = __float2half_rn(v1);
                __half h2 = __float2half_rn(v2), h3 = __float2half_rn(v3);
                *(half2*)&Hout[(size_t)row * Nreal + col]       = __halves2half2(h0, h1);
                *(half2*)&Hout[(size_t)(row + 8) * Nreal + col] = __halves2half2(h2, h3);
                *(half2*)&Lout[(size_t)row * Nreal + col] =
                    __halves2half2(__float2half_rn(v0 - __half2float(h0)),
                                   __float2half_rn(v1 - __half2float(h1)));
                *(half2*)&Lout[(size_t)(row + 8) * Nreal + col] =
                    __halves2half2(__float2half_rn(v2 - __half2float(h2)),
                                   __float2half_rn(v3 - __half2float(h3)));
            }
        }
    }
}

// ============ 1-pass FP16 GEMM (GEMM2/3; 3-stage, 2 CTAs/SM) =================
template<bool HOUT>
__global__ void __launch_bounds__(256, 2) gemm_h1(
    const __half* __restrict__ Ahi, const __half* __restrict__ Bhi,
    float* __restrict__ Cout, __half* __restrict__ HoutP,
    int M, int Nreal, int K)
{
    extern __shared__ __align__(16) char smem[];
    const uint32_t sb = (uint32_t)__cvta_generic_to_shared(smem);
    const int tid = threadIdx.x;
    const int wid = tid >> 5;
    const int lane = tid & 31;
    const int wm = wid & 1;
    const int wn = wid >> 1;
    const int r = lane >> 2;
    const int c = lane & 3;
    const int m0 = blockIdx.y << 7;
    const int n0 = blockIdx.x << 7;
    const int nsteps = K >> 6;

    auto load_stage = [&](int kstep, int s) {
        const int k0 = kstep << 6;
        #pragma unroll
        for (int j = 0; j < 8; j++) {
            const int t = j >> 2;
            const __half* gsel = (t == 0) ? Ahi : Bhi;
            const int rb = (t == 0) ? m0 : n0;
            int rem = ((j & 3) << 8) + tid;
            int row = rem >> 3, col = rem & 7;
            const __half* gp = gsel + (size_t)(rb + row) * K + k0 + (col << 3);
            uint32_t sa = sb + (uint32_t)(s * STAGEB1 + t * TBYTES + row * (HSTRIDE * 2) + (col << 4));
            asm volatile("cp.async.cg.shared.global [%0], [%1], 16;" :: "r"(sa), "l"(gp) : "memory");
        }
        asm volatile("cp.async.commit_group;" ::: "memory");
    };

    float acc[4][4][4];
    #pragma unroll
    for (int i = 0; i < 4; i++)
        #pragma unroll
        for (int j = 0; j < 4; j++)
            #pragma unroll
            for (int q = 0; q < 4; q++) acc[i][j][q] = 0.f;

    const int lrow = lane & 15;
    const int lk16 = (lane >> 4) << 4;
    uint32_t arow_off[4], brow_off[2];
    #pragma unroll
    for (int mt = 0; mt < 4; mt++)
        arow_off[mt] = (uint32_t)((wm * 64 + mt * 16 + lrow) * (HSTRIDE * 2)) + (uint32_t)lk16;
    #pragma unroll
    for (int g = 0; g < 2; g++)
        brow_off[g] = (uint32_t)((wn * 32 + g * 16 + lrow) * (HSTRIDE * 2)) + (uint32_t)lk16;

    load_stage(0, 0);
    if (nsteps > 1) load_stage(1, 1);

    for (int i = 0; i < nsteps; i++) {
        if (i + 2 < nsteps) load_stage(i + 2, (i + 2) % 3);
        const int rem = nsteps - 1 - i;
        if (rem >= 2)      asm volatile("cp.async.wait_group 2;" ::: "memory");
        else if (rem == 1) asm volatile("cp.async.wait_group 1;" ::: "memory");
        else               asm volatile("cp.async.wait_group 0;" ::: "memory");
        __syncthreads();

        const int s = i % 3;
        const uint32_t stA = sb + (uint32_t)(s * STAGEB1);
        const uint32_t stB = stA + TBYTES;

        #pragma unroll
        for (int kb = 0; kb < 4; kb++) {
            const uint32_t koff = (uint32_t)(kb << 5);
            uint32_t ah[4][4], bh[4][2];
            #pragma unroll
            for (int mt = 0; mt < 4; mt++)
                LDSM4(ah[mt][0], ah[mt][1], ah[mt][2], ah[mt][3], stA + arow_off[mt] + koff);
            #pragma unroll
            for (int g = 0; g < 2; g++) {
                uint32_t r0, r1, r2, r3;
                LDSM4(r0, r1, r2, r3, stB + brow_off[g] + koff);
                bh[2*g][0] = r0; bh[2*g+1][0] = r1; bh[2*g][1] = r2; bh[2*g+1][1] = r3;
            }
            #pragma unroll
            for (int mt = 0; mt < 4; mt++)
                #pragma unroll
                for (int nt = 0; nt < 4; nt++) {
                    float* d = acc[mt][nt];
                    mma16(d[0], d[1], d[2], d[3],
                          ah[mt][0], ah[mt][1], ah[mt][2], ah[mt][3], bh[nt][0], bh[nt][1]);
                }
        }
        __syncthreads();
    }

    #pragma unroll
    for (int mt = 0; mt < 4; mt++) {
        const int row = m0 + wm * 64 + mt * 16 + r;
        #pragma unroll
        for (int nt = 0; nt < 4; nt++) {
            const int col = n0 + wn * 32 + nt * 8 + 2 * c;
            if (col < Nreal) {
                if (HOUT) {
                    *(half2*)&HoutP[(size_t)row * Nreal + col] =
                        __halves2half2(__float2half_rn(acc[mt][nt][0]), __float2half_rn(acc[mt][nt][1]));
                    *(half2*)&HoutP[(size_t)(row + 8) * Nreal + col] =
                        __halves2half2(__float2half_rn(acc[mt][nt][2]), __float2half_rn(acc[mt][nt][3]));
                } else {
                    *(float2*)&Cout[(size_t)row * Nreal + col] =
                        make_float2(acc[mt][nt][0], acc[mt][nt][1]);
                    *(float2*)&Cout[(size_t)(row + 8) * Nreal + col] =
                        make_float2(acc[mt][nt][2], acc[mt][nt][3]);
                }
            }
        }
    }
}

// ---------------- elementwise split: float -> (hi, lo) fp16 pair -------------
__global__ void split4h_kernel(const float* __restrict__ x,
                               __half* __restrict__ hi, __half* __restrict__ lo, int n4)
{
    int i = blockIdx.x * blockDim.x + threadIdx.x;
    if (i >= n4) return;
    float4 v = ((const float4*)x)[i];
    __half h0 = __float2half_rn(v.x), h1 = __float2half_rn(v.y);
    __half h2 = __float2half_rn(v.z), h3 = __float2half_rn(v.w);
    ((half2*)hi)[2*i]   = __halves2half2(h0, h1);
    ((half2*)hi)[2*i+1] = __halves2half2(h2, h3);
    ((half2*)lo)[2*i]   = __halves2half2(__float2half_rn(v.x - __half2float(h0)),
                                         __float2half_rn(v.y - __half2float(h1)));
    ((half2*)lo)[2*i+1] = __halves2half2(__float2half_rn(v.z - __half2float(h2)),
                                         __float2half_rn(v.w - __half2float(h3)));
}

// ---------------- transpose + split: W[K,N] -> Wt_hi(/lo)[Npad,K] fp16 -------
template<bool WLO>
__global__ void tsplit_kernel(const float* __restrict__ W,
                              __half* __restrict__ Thi, __half* __restrict__ Tlo,
                              int K, int N)
{
    __shared__ float t[32][33];
    const int n0 = blockIdx.x * 32, k0 = blockIdx.y * 32;
    const int tx = threadIdx.x, ty = threadIdx.y;
    #pragma unroll
    for (int r = 0; r < 4; r++) {
        int k = k0 + ty + r * 8, n = n0 + tx;
        t[ty + r * 8][tx] = (n < N) ? W[(size_t)k * N + n] : 0.f;
    }
    __syncthreads();
    #pragma unroll
    for (int r = 0; r < 4; r++) {
        int n = n0 + ty + r * 8, k = k0 + tx;
        float v = t[tx][ty + r * 8];
        __half h = __float2half_rn(v);
        Thi[(size_t)n * K + k] = h;
        if (WLO) Tlo[(size_t)n * K + k] = __float2half_rn(v - __half2float(h));
    }
}

// ---------------- dt: exact fp32 dt_raw + dtmod + softplus; stores dt, dt*A --
__global__ void __launch_bounds__(256) dt_kernel(
    const float* __restrict__ dte, const float* __restrict__ Wd,
    const float* __restrict__ bd,  const float* __restrict__ W_in,
    const float* __restrict__ dt_bias, const float* __restrict__ A_log)
{
    __shared__ float us[8][1024];
    const int row0 = blockIdx.x * 8;
    const int tid = threadIdx.x;
    for (int idx = tid; idx < 8 * 1024; idx += 256) {
        int r = idx >> 10, j = idx & 1023;
        us[r][j] = __half2float(g_uhi[(size_t)(row0 + r) * DM + j])
                 + __half2float(g_ulo[(size_t)(row0 + r) * DM + j]);
    }
    __syncthreads();
    const int r = tid >> 5, h = tid & 31;
    const int row = row0 + r;
    float s = bd[h];
    #pragma unroll 8
    for (int j = 0; j < DTIME; j++) s = fmaf(dte[(size_t)row * DTIME + j], Wd[j * NH + h], s);
    const float* wcol = W_in + (DI + CD) + h;
    float x0 = 0.f, x1 = 0.f, x2 = 0.f, x3 = 0.f;
    #pragma unroll 4
    for (int j = 0; j < DM; j += 4) {
        x0 = fmaf(us[r][j+0], wcol[(size_t)(j+0) * DIP], x0);
        x1 = fmaf(us[r][j+1], wcol[(size_t)(j+1) * DIP], x1);
        x2 = fmaf(us[r][j+2], wcol[(size_t)(j+2) * DIP], x2);
        x3 = fmaf(us[r][j+3], wcol[(size_t)(j+3) * DIP], x3);
    }
    float x = (x0 + x1) + (x2 + x3) + dt_bias[h] + s;
    float dt = (x > 20.f) ? x : log1pf(expf(x));
    float A  = -expf(A_log[h]);
    const int idx = row * NH + h;
    g_dt[idx]  = dt;
    g_dtA[idx] = dt * A;
}

// ---------------- causal conv (taps=4) + bias + silu; half2-vectorized -------
__global__ void conv_kernel(const float* __restrict__ conv_w,
                            const float* __restrict__ conv_b)
{
    int idx = blockIdx.x * blockDim.x + threadIdx.x;   // over ROWS*CD/2
    if (idx >= ROWS * (CD / 2)) return;
    int c2  = idx % (CD / 2);
    int row = idx / (CD / 2);
    int c   = c2 * 2;
    int l   = row & (L_SZ - 1);
    int b   = row / L_SZ;
    float a0 = conv_b[c], a1 = conv_b[c + 1];
    #pragma unroll
    for (int k = 0; k < DCONV; k++) {
        int ll = l - (DCONV - 1) + k;
        if (ll >= 0) {
            half2 xv = *(const half2*)&g_zxh[(size_t)(b*L_SZ + ll) * NGEMM2 + DI + c];
            float2 xf = __half22float2(xv);
            a0 = fmaf(xf.x, conv_w[k*CD + c],     a0);
            a1 = fmaf(xf.y, conv_w[k*CD + c + 1], a1);
        }
    }
    float s0 = a0 / (1.f + expf(-a0));
    float s1 = a1 / (1.f + expf(-a1));
    *(half2*)&g_xBCh[(size_t)row * CD + c] =
        __halves2half2(__float2half_rn(s0), __float2half_rn(s1));
}

// ================= chunk_state: logcum/cumdec + Sfinal = Xw^T @ B ===========
#define CS_SXTW 0
#define CS_SBT  (64*HS2*2)                 // 17408
#define CS_LCS  (CS_SBT + 128*HS2*2)       // 52224
#define CS_DTV  (CS_LCS + 512)
#define CS_WQ   (CS_DTV + 512)
#define CS_SMEM (CS_WQ + 512)              // 53760
__global__ void __launch_bounds__(256, 2) chunk_state_kernel()
{
    extern __shared__ __align__(16) char sm[];
    __half* sXTw = (__half*)(sm + CS_SXTW);
    __half* sBT  = (__half*)(sm + CS_SBT);
    float*  lcs  = (float*)(sm + CS_LCS);
    float*  dtv  = (float*)(sm + CS_DTV);
    float*  wq   = (float*)(sm + CS_WQ);
    const uint32_t sb = (uint32_t)__cvta_generic_to_shared(sm);

    const int c = blockIdx.x, h = blockIdx.y, b = blockIdx.z;
    const int t = threadIdx.x;
    const int l0 = c * CL;
    const int bh = b * NH + h;

    for (int idx = t; idx < CL * DS; idx += 256) {
        int j = idx >> 7, n = idx & 127;
        sBT[n * HS2 + j] = g_xBCh[(size_t)(b*L_SZ + l0 + j) * CD + DI + n];
    }
    if (t < CL) {
        dtv[t] = g_dt [(b*L_SZ + l0 + t) * NH + h];
        lcs[t] = g_dtA[(b*L_SZ + l0 + t) * NH + h];
    }
    __syncthreads();
    for (int off = 1; off < CL; off <<= 1) {
        float cur = 0.f, v = 0.f;
        if (t < CL) { cur = lcs[t]; if (t >= off) v = lcs[t - off]; }
        __syncthreads();
        if (t < CL) lcs[t] = cur + v;
        __syncthreads();
    }
    if (t < CL) {
        float lc = lcs[t];
        g_logcum[bh*L_SZ + l0 + t] = lc;
        g_cumdec[bh*L_SZ + l0 + t] = __expf(lc);
    }
    __syncthreads();
    const float lcL = lcs[CL - 1];
    if (t < CL) wq[t] = dtv[t] * __expf(lcL - lcs[t]);
    __syncthreads();
    for (int idx = t; idx < CL * HD; idx += 256) {
        int j = idx >> 6, p = idx & 63;
        float v = __half2float(g_xBCh[(size_t)(b*L_SZ + l0 + j) * CD + h*HD + p]);
        sXTw[p * HS2 + j] = __float2half_rn(v * wq[j]);
    }
    __syncthreads();

    const int wid = t >> 5, lane = t & 31;
    const int wm = wid & 1, wn = wid >> 1;
    const int r = lane >> 2, cc = lane & 3;
    const int lrow = lane & 15, lk16 = (lane >> 4) << 4;
    uint32_t aoff[2], boff[2];
    #pragma unroll
    for (int mt = 0; mt < 2; mt++)
        aoff[mt] = sb + CS_SXTW + (uint32_t)((wm*32 + mt*16 + lrow) * (HS2*2)) + (uint32_t)lk16;
    #pragma unroll
    for (int g = 0; g < 2; g++)
        boff[g] = sb + CS_SBT + (uint32_t)((wn*32 + g*16 + lrow) * (HS2*2)) + (uint32_t)lk16;

    float acc[2][4][4];
    #pragma unroll
    for (int i = 0; i < 2; i++)
        #pragma unroll
        for (int j = 0; j < 4; j++)
            #pragma unroll
            for (int q = 0; q < 4; q++) acc[i][j][q] = 0.f;

    #pragma unroll
    for (int kb = 0; kb < 8; kb++) {
        const uint32_t koff = (uint32_t)(kb << 5);
        uint32_t ah[2][4], bhf[4][2];
        #pragma unroll
        for (int mt = 0; mt < 2; mt++)
            LDSM4(ah[mt][0], ah[mt][1], ah[mt][2], ah[mt][3], aoff[mt] + koff);
        #pragma unroll
        for (int g = 0; g < 2; g++) {
            uint32_t r0, r1, r2, r3;
            LDSM4(r0, r1, r2, r3, boff[g] + koff);
            bhf[2*g][0] = r0; bhf[2*g+1][0] = r1; bhf[2*g][1] = r2; bhf[2*g+1][1] = r3;
        }
        #pragma unroll
        for (int mt = 0; mt < 2; mt++)
            #pragma unroll
            for (int nt = 0; nt < 4; nt++) {
                float* d = acc[mt][nt];
                mma16(d[0], d[1], d[2], d[3],
                      ah[mt][0], ah[mt][1], ah[mt][2], ah[mt][3], bhf[nt][0], bhf[nt][1]);
            }
    }
    const size_t sbase = ((size_t)bh * NC + c) * (HD * DS);
    #pragma unroll
    for (int mt = 0; mt < 2; mt++) {
        const int p0 = wm*32 + mt*16 + r;
        #pragma unroll
        for (int nt = 0; nt < 4; nt++) {
            const int n0 = wn*32 + nt*8 + 2*cc;
            *(half2*)&g_SfinalH[sbase + (size_t)p0 * DS + n0] =
                __halves2half2(__float2half_rn(acc[mt][nt][0]), __float2half_rn(acc[mt][nt][1]));
            *(half2*)&g_SfinalH[sbase + (size_t)(p0+8) * DS + n0] =
                __halves2half2(__float2half_rn(acc[mt][nt][2]), __float2half_rn(acc[mt][nt][3]));
        }
    }
}

// ---------------- phase B: sequential chunk-state combine (fp32 accum) -------
__global__ void phaseB_kernel()
{
    const int bh = blockIdx.x;
    const int e0 = blockIdx.y * 1024;
    const int t  = threadIdx.x;
    __shared__ float Ps[NC];
    if (t < NC) Ps[t] = g_cumdec[bh*L_SZ + t*CL + CL - 1];
    __syncthreads();
    for (int e = e0 + t; e < e0 + 1024; e += 256) {
        float hv = 0.f;
        for (int c = 0; c < NC; c++) {
            const size_t o = ((size_t)bh * NC + c) * (HD * DS) + e;
            g_HinitH[o] = __float2half_rn(hv);
            hv = fmaf(Ps[c], hv, __half2float(g_SfinalH[o]));
        }
    }
}

// ================ chunk_out: Y = (CB^T o M o dt) @ X + cum*(C@H^T) + D*x =====
#define CO_SC   0
#define CO_SB   (128*HS2*2)                 // 34816
#define CO_SXT  (2*128*HS2*2)               // 69632
#define CO_SH   (CO_SXT + 64*HS2*2)         // 87040
#define CO_LC   (CO_SH + 64*HS2*2)          // 104448
#define CO_DT   (CO_LC + 512)
#define CO_SMEM (CO_DT + 512)               // 105472
__global__ void __launch_bounds__(256, 2) chunk_out_kernel(const float* __restrict__ Dvec)
{
    extern __shared__ __align__(16) char sm[];
    __half* sC  = (__half*)(sm + CO_SC);
    __half* sB  = (__half*)(sm + CO_SB);    // becomes sW after G
    __half* sXT = (__half*)(sm + CO_SXT);
    __half* sH  = (__half*)(sm + CO_SH);
    float*  lc  = (float*)(sm + CO_LC);
    float*  dtw = (float*)(sm + CO_DT);
    const uint32_t sb = (uint32_t)__cvta_generic_to_shared(sm);

    const int c = blockIdx.x, h = blockIdx.y, b = blockIdx.z;
    const int t = threadIdx.x;
    const int l0 = c * CL;
    const int bh = b * NH + h;
    const bool do_corr = (c != 0);

    for (int idx = t; idx < CL * 16; idx += 256) {
        int l = idx >> 4, q = idx & 15;
        const __half* base = g_xBCh + (size_t)(b*L_SZ + l0 + l) * CD;
        *(uint4*)&sC[l * HS2 + q * 8] = *(const uint4*)&base[DI + DS + q * 8];
        *(uint4*)&sB[l * HS2 + q * 8] = *(const uint4*)&base[DI + q * 8];
    }
    for (int idx = t; idx < CL * HD; idx += 256) {
        int l = idx >> 6, p = idx & 63;
        sXT[p * HS2 + l] = g_xBCh[(size_t)(b*L_SZ + l0 + l) * CD + h*HD + p];
    }
    const size_t hbase = ((size_t)bh * NC + c) * (HD * DS);
    if (do_corr) {
        for (int idx = t; idx < HD * 16; idx += 256) {
            int p = idx >> 4, q = idx & 15;
            *(uint4*)&sH[p * HS2 + q * 8] = *(const uint4*)&g_HinitH[hbase + (size_t)p * DS + q * 8];
        }
    } else {
        uint4 z = make_uint4(0, 0, 0, 0);
        for (int idx = t; idx < HD * 16; idx += 256) {
            int p = idx >> 4, q = idx & 15;
            *(uint4*)&sH[p * HS2 + q * 8] = z;
        }
    }
    if (t < CL) {
        lc[t]  = g_logcum[bh*L_SZ + l0 + t];
        dtw[t] = g_dt[(b*L_SZ + l0 + t) * NH + h];
    }
    __syncthreads();

    const int wid = t >> 5, lane = t & 31;
    const int wm = wid & 3;
    const int wn = wid >> 2;
    const int r = lane >> 2, cc = lane & 3;
    const int lrow = lane & 15, lk16 = (lane >> 4) << 4;

    uint32_t aoffC[2], aoffW[2], boffB[4], boffX[2], boffH[2];
    #pragma unroll
    for (int mt = 0; mt < 2; mt++) {
        uint32_t ro = (uint32_t)((wm*32 + mt*16 + lrow) * (HS2*2)) + (uint32_t)lk16;
        aoffC[mt] = sb + CO_SC + ro;
        aoffW[mt] = sb + CO_SB + ro;
    }
    #pragma unroll
    for (int g = 0; g < 4; g++)
        boffB[g] = sb + CO_SB + (uint32_t)((wn*64 + g*16 + lrow) * (HS2*2)) + (uint32_t)lk16;
    #pragma unroll
    for (int g = 0; g < 2; g++) {
        uint32_t ro = (uint32_t)((wn*32 + g*16 + lrow) * (HS2*2)) + (uint32_t)lk16;
        boffX[g] = sb + CO_SXT + ro;
        boffH[g] = sb + CO_SH + ro;
    }

    // ---- G = C @ B^T
    float G[2][8][4];
    #pragma unroll
    for (int i = 0; i < 2; i++)
        #pragma unroll
        for (int j = 0; j < 8; j++)
            #pragma unroll
            for (int q = 0; q < 4; q++) G[i][j][q] = 0.f;
    #pragma unroll
    for (int kb = 0; kb < 8; kb++) {
        const uint32_t koff = (uint32_t)(kb << 5);
        uint32_t ah[2][4], bhf[8][2];
        #pragma unroll
        for (int mt = 0; mt < 2; mt++)
            LDSM4(ah[mt][0], ah[mt][1], ah[mt][2], ah[mt][3], aoffC[mt] + koff);
        #pragma unroll
        for (int g = 0; g < 4; g++) {
            uint32_t r0, r1, r2, r3;
            LDSM4(r0, r1, r2, r3, boffB[g] + koff);
            bhf[2*g][0] = r0; bhf[2*g+1][0] = r1; bhf[2*g][1] = r2; bhf[2*g+1][1] = r3;
        }
        #pragma unroll
        for (int mt = 0; mt < 2; mt++)
            #pragma unroll
            for (int nt = 0; nt < 8; nt++) {
                float* d = G[mt][nt];
                mma16(d[0], d[1], d[2], d[3],
                      ah[mt][0], ah[mt][1], ah[mt][2], ah[mt][3], bhf[nt][0], bhf[nt][1]);
            }
    }
    __syncthreads();

    // ---- W[l][j] = G * dt_j * exp(lc_l - lc_j), causal
    __half* sW = sB;
    #pragma unroll
    for (int mt = 0; mt < 2; mt++) {
        const int lr0 = wm*32 + mt*16 + r;
        const int lr1 = lr0 + 8;
        const float lc0 = lc[lr0], lc1 = lc[lr1];
        #pragma unroll
        for (int nt = 0; nt < 8; nt++) {
            const int j0 = wn*64 + nt*8 + 2*cc;
            const int j1 = j0 + 1;
            const float dj0 = dtw[j0], dj1 = dtw[j1];
            const float lj0 = lc[j0], lj1 = lc[j1];
            float w00 = (j0 <= lr0) ? G[mt][nt][0] * dj0 * __expf(lc0 - lj0) : 0.f;
            float w01 = (j1 <= lr0) ? G[mt][nt][1] * dj1 * __expf(lc0 - lj1) : 0.f;
            float w10 = (j0 <= lr1) ? G[mt][nt][2] * dj0 * __expf(lc1 - lj0) : 0.f;
            float w11 = (j1 <= lr1) ? G[mt][nt][3] * dj1 * __expf(lc1 - lj1) : 0.f;
            *(half2*)&sW[lr0 * HS2 + j0] = __halves2half2(__float2half_rn(w00), __float2half_rn(w01));
            *(half2*)&sW[lr1 * HS2 + j0] = __halves2half2(__float2half_rn(w10), __float2half_rn(w11));
        }
    }
    __syncthreads();

    // ---- Y = W @ X^T ; R = C @ H^T
    float Y[2][4][4], R[2][4][4];
    #pragma unroll
    for (int i = 0; i < 2; i++)
        #pragma unroll
        for (int j = 0; j < 4; j++)
            #pragma unroll
            for (int q = 0; q < 4; q++) { Y[i][j][q] = 0.f; R[i][j][q] = 0.f; }
    #pragma unroll
    for (int kb = 0; kb < 8; kb++) {
        const uint32_t koff = (uint32_t)(kb << 5);
        uint32_t ah[2][4], bhf[4][2];
        #pragma unroll
        for (int mt = 0; mt < 2; mt++)
            LDSM4(ah[mt][0], ah[mt][1], ah[mt][2], ah[mt][3], aoffW[mt] + koff);
        #pragma unroll
        for (int g = 0; g < 2; g++) {
            uint32_t r0, r1, r2, r3;
            LDSM4(r0, r1, r2, r3, boffX[g] + koff);
            bhf[2*g][0] = r0; bhf[2*g+1][0] = r1; bhf[2*g][1] = r2; bhf[2*g+1][1] = r3;
        }
        #pragma unroll
        for (int mt = 0; mt < 2; mt++)
            #pragma unroll
            for (int nt = 0; nt < 4; nt++) {
                float* d = Y[mt][nt];
                mma16(d[0], d[1], d[2], d[3],
                      ah[mt][0], ah[mt][1], ah[mt][2], ah[mt][3], bhf[nt][0], bhf[nt][1]);
            }
    }
    if (do_corr) {
        #pragma unroll
        for (int kb = 0; kb < 8; kb++) {
            const uint32_t koff = (uint32_t)(kb << 5);
            uint32_t ah[2][4], bhf[4][2];
            #pragma unroll
            for (int mt = 0; mt < 2; mt++)
                LDSM4(ah[mt][0], ah[mt][1], ah[mt][2], ah[mt][3], aoffC[mt] + koff);
            #pragma unroll
            for (int g = 0; g < 2; g++) {
                uint32_t r0, r1, r2, r3;
                LDSM4(r0, r1, r2, r3, boffH[g] + koff);
                bhf[2*g][0] = r0; bhf[2*g+1][0] = r1; bhf[2*g][1] = r2; bhf[2*g+1][1] = r3;
            }
            #pragma unroll
            for (int mt = 0; mt < 2; mt++)
                #pragma unroll
                for (int nt = 0; nt < 4; nt++) {
                    float* d = R[mt][nt];
                    mma16(d[0], d[1], d[2], d[3],
                          ah[mt][0], ah[mt][1], ah[mt][2], ah[mt][3], bhf[nt][0], bhf[nt][1]);
                }
        }
    }

    // ---- epilogue: y = Y + exp(lc_l)*R + D*x  (fp16 out)
    const float Dh = Dvec[h];
    #pragma unroll
    for (int mt = 0; mt < 2; mt++) {
        #pragma unroll
        for (int half = 0; half < 2; half++) {
            const int lrw = wm*32 + mt*16 + r + half*8;
            const float cum = __expf(lc[lrw]);
            const size_t grow = (size_t)(b*L_SZ + l0 + lrw);
            #pragma unroll
            for (int nt = 0; nt < 4; nt++) {
                const int p0 = wn*32 + nt*8 + 2*cc;
                half2 xh = *(const half2*)&g_xBCh[grow * CD + h*HD + p0];
                float2 xv = __half22float2(xh);
                float y0 = Y[mt][nt][2*half+0] + cum * R[mt][nt][2*half+0] + Dh * xv.x;
                float y1 = Y[mt][nt][2*half+1] + cum * R[mt][nt][2*half+1] + Dh * xv.y;
                *(half2*)&g_yh[grow * DI + h*HD + p0] =
                    __halves2half2(__float2half_rn(y0), __float2half_rn(y1));
            }
        }
    }
}

// ---------------- gating (silu(z)) + RMS norm -> fp16 hi ---------------------
__global__ void __launch_bounds__(256) epilogue_kernel(const float* __restrict__ norm_w)
{
    const int row = blockIdx.x;
    const int t   = threadIdx.x;
    float gv[8];
    float ss = 0.f;
    #pragma unroll
    for (int i = 0; i < 4; i++) {
        int base = (t + i * 256) * 2;
        float2 yv = __half22float2(*(const half2*)&g_yh[(size_t)row * DI + base]);
        float2 zv = __half22float2(*(const half2*)&g_zxh[(size_t)row * NGEMM2 + base]);
        float s0 = zv.x / (1.f + expf(-zv.x));
        float s1 = zv.y / (1.f + expf(-zv.y));
        float v0 = yv.x * s0, v1 = yv.y * s1;
        gv[2*i] = v0; gv[2*i+1] = v1;
        ss += v0 * v0 + v1 * v1;
    }
    __shared__ float rs[32];
    #pragma unroll
    for (int o = 16; o; o >>= 1) ss += __shfl_xor_sync(~0u, ss, o);
    if ((t & 31) == 0) rs[t >> 5] = ss;
    __syncthreads();
    if (t < 32) {
        float v = (t < 8) ? rs[t] : 0.f;
        #pragma unroll
        for (int o = 4; o; o >>= 1) v += __shfl_xor_sync(~0u, v, o);
        if (t == 0) rs[0] = v;
    }
    __syncthreads();
    float scale = rsqrtf(rs[0] / (float)DI + EPSV);
    #pragma unroll
    for (int i = 0; i < 4; i++) {
        int base = (t + i * 256) * 2;
        float v0 = gv[2*i]   * scale * norm_w[base];
        float v1 = gv[2*i+1] * scale * norm_w[base+1];
        *(half2*)&g_yhi[(size_t)row * DI + base] =
            __halves2half2(__float2half_rn(v0), __float2half_rn(v1));
    }
}

// ---------------- launch ----------------
extern "C" void kernel_launch(void* const* d_in, const int* in_sizes, int n_in,
                              void* d_out, int out_size)
{
    const float* hidden  = (const float*)d_in[0];
    const float* dte     = (const float*)d_in[1];
    const float* W_proj  = (const float*)d_in[2];
    const float* b_proj  = (const float*)d_in[3];
    const float* W_dtmod = (const float*)d_in[4];
    const float* b_dtmod = (const float*)d_in[5];
    const float* W_in    = (const float*)d_in[6];
    const float* conv_w  = (const float*)d_in[7];
    const float* conv_b  = (const float*)d_in[8];
    const float* dt_bias = (const float*)d_in[9];
    const float* A_log   = (const float*)d_in[10];
    const float* Dvec    = (const float*)d_in[11];
    const float* norm_w  = (const float*)d_in[12];
    const float* W_out   = (const float*)d_in[13];
    float* out = (float*)d_out;

    __half *p_uhi, *p_ulo, *p_yhi, *p_hhi, *p_hlo, *p_zxh;
    __half *p_wpt_hi, *p_wpt_lo, *p_wit_hi, *p_wot_hi;
    cudaGetSymbolAddress((void**)&p_uhi, g_uhi);
    cudaGetSymbolAddress((void**)&p_ulo, g_ulo);
    cudaGetSymbolAddress((void**)&p_zxh, g_zxh);
    cudaGetSymbolAddress((void**)&p_yhi, g_yhi);
    cudaGetSymbolAddress((void**)&p_hhi, g_hhi);
    cudaGetSymbolAddress((void**)&p_hlo, g_hlo);
    cudaGetSymbolAddress((void**)&p_wpt_hi, g_wpt_hi);
    cudaGetSymbolAddress((void**)&p_wpt_lo, g_wpt_lo);
    cudaGetSymbolAddress((void**)&p_wit_hi, g_wit_hi);
    cudaGetSymbolAddress((void**)&p_wot_hi, g_wot_hi);

    cudaFuncSetAttribute(gemm_h3, cudaFuncAttributeMaxDynamicSharedMemorySize, SMEM3P);
    cudaFuncSetAttribute(gemm_h1<true >, cudaFuncAttributeMaxDynamicSharedMemorySize, SMEM1P);
    cudaFuncSetAttribute(gemm_h1<false>, cudaFuncAttributeMaxDynamicSharedMemorySize, SMEM1P);
    cudaFuncSetAttribute(chunk_state_kernel, cudaFuncAttributeMaxDynamicSharedMemorySize, CS_SMEM);
    cudaFuncSetAttribute(chunk_out_kernel,   cudaFuncAttributeMaxDynamicSharedMemorySize, CO_SMEM);

    // 0) operand prep
    split4h_kernel<<<(ROWS*DM/4 + 255)/256, 256>>>(hidden, p_hhi, p_hlo, ROWS*DM/4);
    tsplit_kernel<true ><<<dim3(DM/32,  DM/32), dim3(32,8)>>>(W_proj, p_wpt_hi, p_wpt_lo, DM, DM);
    tsplit_kernel<false><<<dim3(DIPPAD/32, DM/32), dim3(32,8)>>>(W_in,  p_wit_hi, nullptr, DM, DIP);
    tsplit_kernel<false><<<dim3(DM/32,  DI/32), dim3(32,8)>>>(W_out, p_wot_hi, nullptr, DI, DM);

    // 1) u = hidden @ W_proj + b_proj   (3-pass; split fp16 output)
    gemm_h3<<<dim3(DM/128, ROWS/128), 512, SMEM3P>>>(
        p_hhi, p_hlo, p_wpt_hi, p_wpt_lo, b_proj, p_uhi, p_ulo, ROWS, DM, DM);

    // 2) zxbcdt[:, :4352] = u @ W_in   (1-pass, fp16 output)
    gemm_h1<true><<<dim3(NGEMM2/128, ROWS/128), 256, SMEM1P>>>(
        p_uhi, p_wit_hi, nullptr, p_zxh, ROWS, NGEMM2, DM);

    // 3) dt exact (from split u against fp32 W_in column)
    dt_kernel<<<ROWS/8, 256>>>(dte, W_dtmod, b_dtmod, W_in, dt_bias, A_log);

    // 4) conv + silu (half2 vectorized)
    conv_kernel<<<(ROWS*CD/2 + 255)/256, 256>>>(conv_w, conv_b);

    // 5) chunked scan in matmul form (tensor-core; fp16 state)
    chunk_state_kernel<<<dim3(NC, NH, B_SZ), 256, CS_SMEM>>>();
    phaseB_kernel<<<dim3(B_SZ*NH, 8), 256>>>();
    chunk_out_kernel<<<dim3(NC, NH, B_SZ), 256, CO_SMEM>>>(Dvec);

    // 6) gating + RMS norm
    epilogue_kernel<<<ROWS, 256>>>(norm_w);

    // 7) out = yn @ W_out   (1-pass, fp32 output)
    gemm_h1<false><<<dim3(DM/128, ROWS/128), 256, SMEM1P>>>(
        p_yhi, p_wot_hi, out, nullptr, ROWS, DM, DI);
}